// round 6
// baseline (speedup 1.0000x reference)
#include <cuda_runtime.h>
#include <math.h>
#include <stdint.h>

#define Nn    4096
#define DIMS  64
#define NNt   (Nn*Nn)
#define NB1   1024
#define SH1   16
#define NB2   131072           /* two 65536-key exact regions */
#define KB    0xC0800000u      /* f2k(4.0f) */
#define SPAN1 0x04000000u      /* 2^26 keys: values [4,1024) */
/* ranks (0-indexed, ascending) of the two triu-median values in the FULL
   n^2 multiset: triu ranks m/2-1, m/2 (m=n(n-1)/2) each doubled, plus
   4096 diagonal (~0) entries below everything */
#define R_LO 8390655u
#define R_HI 8390656u
#define TNT   32               /* tile grid dim: 4096/128 */
#define TILES 528              /* upper-tri tiles incl diagonal */

// ------------- device scratch (globals: no allocations allowed) -------------
__device__ float    g_D[2][NNt];
__device__ float    g_G[2][Nn];
__device__ unsigned g_hist1[2][NB1];
__device__ unsigned g_below1[2];
__device__ unsigned g_W1[2], g_W2[2];
__device__ unsigned g_hist2[2][NB2];
__device__ unsigned g_below2[2];
__device__ float    g_c[2];          // -log2(e)/median
__device__ double   g_rowd[2][Nn];
__device__ float    g_rmf[2][Nn];
__device__ float    g_tmf[2];
__device__ double   g_totd[2];
__device__ double   g_part[5][TILES];

__device__ __forceinline__ unsigned f2k(float f){
    unsigned u = __float_as_uint(f);
    return (u & 0x80000000u) ? ~u : (u | 0x80000000u);
}
__device__ __forceinline__ float k2f(unsigned k){
    unsigned u = (k & 0x80000000u) ? (k & 0x7FFFFFFFu) : ~k;
    return __uint_as_float(u);
}
// decode linear upper-triangle tile index -> (bi,bj), bi<=bj
__device__ __forceinline__ void tri_decode(int q, int &bi, int &bj){
    int b = (int)((65.0 - sqrt(65.0*65.0 - 8.0*(double)q))*0.5);
    if (b > TNT-1) b = TNT-1;
    while (b*(2*TNT+1-b)/2 > q) b--;
    while ((b+1)*(2*TNT+1-(b+1))/2 <= q) b++;
    bi = b; bj = b + (q - b*(2*TNT+1-b)/2);
}

// ---------------- initA: zero all accumulated state -------------------------
__global__ void k_initA(){
    int idx = blockIdx.x*256 + threadIdx.x;          // 0 .. 262143
    if (idx < 2*NB1) ((unsigned*)g_hist1)[idx] = 0u;
    if (idx < 2*NB2) ((unsigned*)g_hist2)[idx] = 0u;
    if (idx < 2){ g_below1[idx]=0u; g_below2[idx]=0u; }
    if (idx < 2*Nn) ((double*)g_rowd)[idx] = 0.0;
}

// ---------------- initB/C: squared norms (one warp per row) -----------------
__global__ void k_normsX(const float* __restrict__ X){
    int idx = blockIdx.x*256 + threadIdx.x;
    int row = idx >> 5, lane = idx & 31;
    float a = X[row*DIMS + lane];
    float b = X[row*DIMS + lane + 32];
    float s = a*a + b*b;
    #pragma unroll
    for (int off=16; off; off>>=1) s += __shfl_xor_sync(0xffffffffu, s, off);
    if (lane==0) g_G[0][row] = s;
}
__global__ void k_normsY(const float* __restrict__ Y){
    int idx = blockIdx.x*256 + threadIdx.x;
    int row = idx >> 5, lane = idx & 31;
    float a = Y[row*DIMS + lane];
    float b = Y[row*DIMS + lane + 32];
    float s = a*a + b*b;
    #pragma unroll
    for (int off=16; off; off>>=1) s += __shfl_xor_sync(0xffffffffu, s, off);
    if (lane==0) g_G[1][row] = s;
}

// ---- upper-tri distance tiles: D = Gi+Gj-2*dot (8x8 reg tile + fused hist) --
__global__ void __launch_bounds__(256) k_dist(const float* __restrict__ X,
                                              const float* __restrict__ Y){
    const int mat = blockIdx.y;
    const float* A = mat ? Y : X;
    float* D = g_D[mat];
    const float* G = g_G[mat];
    int bi, bj; tri_decode(blockIdx.x, bi, bj);
    int i0 = bi*128, j0 = bj*128;
    __shared__ float As[128][33];
    __shared__ float Bs[128][33];
    __shared__ unsigned hb[NB1+1];    // [NB1] = below-4.0 counter
    int t = threadIdx.x;
    int tx = t & 15, ty = t >> 4;
    for (int b=t; b<NB1+1; b+=256) hb[b]=0u;

    float acc[8][8];
    #pragma unroll
    for (int a=0;a<8;a++)
        #pragma unroll
        for (int b=0;b<8;b++) acc[a][b]=0.0f;

    for (int kk=0; kk<64; kk+=32){
        __syncthreads();
        #pragma unroll
        for (int it=0; it<4; it++){
            int l = t + it*256;          // 0..1023 float4 slots
            int r = l >> 3, c4 = l & 7;
            float4 va = *(const float4*)&A[(i0+r)*DIMS + kk + c4*4];
            As[r][c4*4+0]=va.x; As[r][c4*4+1]=va.y; As[r][c4*4+2]=va.z; As[r][c4*4+3]=va.w;
            float4 vb = *(const float4*)&A[(j0+r)*DIMS + kk + c4*4];
            Bs[r][c4*4+0]=vb.x; Bs[r][c4*4+1]=vb.y; Bs[r][c4*4+2]=vb.z; Bs[r][c4*4+3]=vb.w;
        }
        __syncthreads();
        #pragma unroll 8
        for (int k=0;k<32;k++){
            float ar[8], br[8];
            #pragma unroll
            for (int a=0;a<8;a++) ar[a] = As[ty+16*a][k];
            #pragma unroll
            for (int b=0;b<8;b++) br[b] = Bs[tx+16*b][k];
            #pragma unroll
            for (int a=0;a<8;a++)
                #pragma unroll
                for (int b=0;b<8;b++) acc[a][b] += ar[a]*br[b];
        }
    }

    unsigned w = (bi==bj) ? 1u : 2u;
    float gi[8], gj[8];
    #pragma unroll
    for (int a=0;a<8;a++) gi[a] = G[i0+ty+16*a];
    #pragma unroll
    for (int b=0;b<8;b++) gj[b] = G[j0+tx+16*b];
    #pragma unroll
    for (int a=0;a<8;a++){
        int i = i0 + ty + 16*a;
        #pragma unroll
        for (int b=0;b<8;b++){
            int j = j0 + tx + 16*b;
            float v = gi[a] + gj[b] - 2.0f*acc[a][b];
            D[(size_t)i*Nn + j] = v;
            unsigned key = f2k(v);
            unsigned off = key - KB;
            if (off < SPAN1) atomicAdd(&hb[off>>SH1], w);
            else if (key < KB) atomicAdd(&hb[NB1], w);
        }
    }
    __syncthreads();
    for (int b=t; b<NB1; b+=256)
        if (hb[b]) atomicAdd(&g_hist1[mat][b], hb[b]);
    if (t==0 && hb[NB1]) atomicAdd(&g_below1[mat], hb[NB1]);
}

// --------- locate the (<=2) coarse bins holding ranks R_LO / R_HI -----------
__global__ void k_sel1(){
    __shared__ unsigned sh[NB1];
    __shared__ int sb1, sb2;
    int t = threadIdx.x;
    for (int m=0;m<2;m++){
        if (t==0){ sb1=-1; sb2=-1; }
        unsigned c = g_hist1[m][t];
        sh[t]=c; __syncthreads();
        for (int off=1; off<NB1; off<<=1){
            unsigned v = (t>=off) ? sh[t-off] : 0u;
            __syncthreads(); sh[t]+=v; __syncthreads();
        }
        unsigned lo = g_below1[m] + (sh[t]-c);
        unsigned hi = lo + c;
        if (c){
            if (lo<=R_LO && R_LO<hi) sb1 = t;
            if (lo<=R_HI && R_HI<hi) sb2 = t;
        }
        __syncthreads();
        if (t==0){
            int b1=sb1, b2=sb2;
            if (b1<0) b1 = (b2>=0)? b2 : NB1/2;
            if (b2<0) b2 = b1;
            if (b2==b1) b2 = b1+1;                   // keep regions disjoint
            g_W1[m] = KB + ((unsigned)b1 << SH1);
            g_W2[m] = KB + ((unsigned)b2 << SH1);
        }
        __syncthreads();
    }
}

// ----- exact pass over upper tiles: per-key hist in 2 regions (weighted) ----
__global__ void k_hist2(){
    int mat = blockIdx.y;
    int bi, bj; tri_decode(blockIdx.x, bi, bj);
    int i0 = bi*128, j0 = bj*128;
    unsigned w = (bi==bj) ? 1u : 2u;
    unsigned W1 = g_W1[mat], W2 = g_W2[mat];
    int warp = threadIdx.x >> 5, lane = threadIdx.x & 31;
    unsigned below = 0;
    for (int r = warp; r < 128; r += 8){
        float4 d = *(const float4*)&g_D[mat][(size_t)(i0+r)*Nn + j0 + lane*4];
        #pragma unroll
        for (int c=0;c<4;c++){
            float val = (c==0)?d.x:(c==1)?d.y:(c==2)?d.z:d.w;
            unsigned key = f2k(val);
            unsigned o1 = key - W1;
            if (o1 < 65536u) atomicAdd(&g_hist2[mat][o1], w);
            else {
                unsigned o2 = key - W2;
                if (o2 < 65536u) atomicAdd(&g_hist2[mat][65536u+o2], w);
                else if (key < W1) below += w;
            }
        }
    }
    #pragma unroll
    for (int off=16; off; off>>=1) below += __shfl_xor_sync(0xffffffffu, below, off);
    __shared__ unsigned sb[8];
    if (lane==0) sb[warp]=below;
    __syncthreads();
    if (threadIdx.x==0){
        unsigned s=0;
        for (int q=0;q<8;q++) s+=sb[q];
        if (s) atomicAdd(&g_below2[mat], s);
    }
}

// ----------- exact median keys -> width -> c = -log2(e)/median --------------
__global__ void k_sel2(){
    __shared__ unsigned sh[1024];
    __shared__ int so1, so2;
    int t = threadIdx.x;
    for (int m=0;m<2;m++){
        if (t==0){ so1=-1; so2=-1; }
        unsigned local=0;
        for (int q=0;q<128;q++) local += g_hist2[m][t*128+q];
        sh[t]=local; __syncthreads();
        for (int off=1; off<1024; off<<=1){
            unsigned v = (t>=off) ? sh[t-off] : 0u;
            __syncthreads(); sh[t]+=v; __syncthreads();
        }
        unsigned run = g_below2[m] + (sh[t]-local);
        for (int q=0;q<128;q++){
            unsigned cnt = g_hist2[m][t*128+q];
            unsigned lo=run, hi=run+cnt;
            if (cnt){
                if (lo<=R_LO && R_LO<hi) so1 = t*128+q;
                if (lo<=R_HI && R_HI<hi) so2 = t*128+q;
            }
            run=hi;
        }
        __syncthreads();
        if (t==0){
            unsigned W1=g_W1[m], W2=g_W2[m];
            int o1=so1, o2=so2;
            if (o1<0 && o2>=0) o1=o2;
            if (o2<0 && o1>=0) o2=o1;
            if (o1<0){ o1=32768; o2=32768; }         // unreachable safety
            unsigned k1 = (o1<65536)? W1+(unsigned)o1 : W2+(unsigned)(o1-65536);
            unsigned k2 = (o2<65536)? W1+(unsigned)o2 : W2+(unsigned)(o2-65536);
            float med = 0.5f*(k2f(k1)+k2f(k2));      // median == 2*width^2
            g_c[m] = -(float)(1.4426950408889634 / (double)med);
        }
        __syncthreads();
    }
}

// ----- row sums from upper tiles: row partials + transposed col partials ----
__global__ void k_rowsum(){
    int mat = blockIdx.y;
    int bi, bj; tri_decode(blockIdx.x, bi, bj);
    int i0 = bi*128, j0 = bj*128;
    float c = g_c[mat];
    int warp = threadIdx.x >> 5, lane = threadIdx.x & 31;
    float ca0=0.f, ca1=0.f, ca2=0.f, ca3=0.f;
    for (int r = warp; r < 128; r += 8){
        float4 d = *(const float4*)&g_D[mat][(size_t)(i0+r)*Nn + j0 + lane*4];
        float e0=exp2f(d.x*c), e1=exp2f(d.y*c), e2=exp2f(d.z*c), e3=exp2f(d.w*c);
        float rs = (e0+e1)+(e2+e3);
        #pragma unroll
        for (int off=16; off; off>>=1) rs += __shfl_xor_sync(0xffffffffu, rs, off);
        if (lane==0) atomicAdd(&g_rowd[mat][i0+r], (double)rs);
        ca0+=e0; ca1+=e1; ca2+=e2; ca3+=e3;
    }
    if (bi != bj){
        __shared__ float cs[8][128];
        cs[warp][lane*4+0]=ca0; cs[warp][lane*4+1]=ca1;
        cs[warp][lane*4+2]=ca2; cs[warp][lane*4+3]=ca3;
        __syncthreads();
        if (threadIdx.x < 128){
            float s=0.f;
            #pragma unroll
            for (int q=0;q<8;q++) s += cs[q][threadIdx.x];
            atomicAdd(&g_rowd[mat][j0+threadIdx.x], (double)s);
        }
    }
}

__device__ double blockReduceD(double v, double* sh){
    int t = threadIdx.x;
    sh[t]=v; __syncthreads();
    for (int off=512; off; off>>=1){
        if (t<off) sh[t]+=sh[t+off];
        __syncthreads();
    }
    double r = sh[0]; __syncthreads();
    return r;
}

// --------------------- totals + means from row sums -------------------------
__global__ void k_prep(){
    __shared__ double shD[1024];
    int t = threadIdx.x;
    for (int m=0;m<2;m++){
        double s=0.0;
        for (int k=t;k<Nn;k+=1024) s += g_rowd[m][k];
        double tot = blockReduceD(s, shD);
        if (t==0){ g_totd[m]=tot; g_tmf[m]=(float)(tot/((double)Nn*(double)Nn)); }
    }
    for (int k=t;k<2*Nn;k+=1024){
        int m=k>>12, i=k&4095;
        g_rmf[m][i] = (float)(g_rowd[m][i]*(1.0/(double)Nn));
    }
}

// -- fused centered-product over upper tiles (S1,S2 weighted; diag extras) ---
__global__ void k_main(){
    int bi, bj; tri_decode(blockIdx.x, bi, bj);
    int i0 = bi*128, j0 = bj*128;
    bool diag = (bi==bj);
    float cX=g_c[0], cY=g_c[1];
    float tmK=g_tmf[0], tmL=g_tmf[1];
    int warp = threadIdx.x >> 5, lane = threadIdx.x & 31;
    float4 rmKj = *(const float4*)&g_rmf[0][j0 + lane*4];
    float4 rmLj = *(const float4*)&g_rmf[1][j0 + lane*4];
    float s1=0.f, s2=0.f, s2d=0.f, trk=0.f, trl=0.f;
    for (int r = warp; r < 128; r += 8){
        int i = i0 + r;
        float rmKi = __ldg(&g_rmf[0][i]);
        float rmLi = __ldg(&g_rmf[1][i]);
        float4 dx = *(const float4*)&g_D[0][(size_t)i*Nn + j0 + lane*4];
        float4 dy = *(const float4*)&g_D[1][(size_t)i*Nn + j0 + lane*4];
        #pragma unroll
        for (int c=0;c<4;c++){
            float dxx = (c==0)?dx.x:(c==1)?dx.y:(c==2)?dx.z:dx.w;
            float dyy = (c==0)?dy.x:(c==1)?dy.y:(c==2)?dy.z:dy.w;
            float rkj = (c==0)?rmKj.x:(c==1)?rmKj.y:(c==2)?rmKj.z:rmKj.w;
            float rlj = (c==0)?rmLj.x:(c==1)?rmLj.y:(c==2)?rmLj.z:rmLj.w;
            float k = exp2f(dxx*cX);
            float l = exp2f(dyy*cY);
            float kc = k - rmKi - rkj + tmK;
            float lc = l - rmLi - rlj + tmL;
            float pr = kc*lc;
            s1 += pr;
            float p6 = pr*(1.0f/6.0f);
            float p66 = p6*p6;
            s2 += p66;
            if (diag && r == lane*4+c){ s2d += p66; trk += k; trl += l; }
        }
    }
    double wgt = diag ? 1.0 : 2.0;
    __shared__ double sd[256];
    double vals[5] = {wgt*(double)s1, wgt*(double)s2, (double)s2d, (double)trk, (double)trl};
    for (int q=0;q<5;q++){
        sd[threadIdx.x]=vals[q]; __syncthreads();
        for (int off=128; off; off>>=1){
            if (threadIdx.x<off) sd[threadIdx.x]+=sd[threadIdx.x+off];
            __syncthreads();
        }
        if (threadIdx.x==0) g_part[q][blockIdx.x]=sd[0];
        __syncthreads();
    }
}

// --------- final scalars + gamma quantile (parallel-series Newton) ----------
__global__ void k_final(float* out){
    __shared__ double shD[1024];
    __shared__ double S[4096];
    int t = threadIdx.x;
    double red[5];
    for (int q=0;q<5;q++){
        double s=0.0;
        for (int k=t;k<TILES;k+=1024) s += g_part[q][k];
        red[q] = blockReduceD(s, shD);
    }
    const double n = (double)Nn;
    double S1=red[0], S2=red[1], S2d=red[2], trK=red[3], trL=red[4];
    double testStat = S1/n;
    double varHSIC = (S2 - S2d)/(n*(n-1.0));
    varHSIC = varHSIC * 72.0*(n-4.0)*(n-5.0)/(n*(n-1.0)*(n-2.0)*(n-3.0));
    double muX = (g_totd[0]-trK)/(n*(n-1.0));
    double muY = (g_totd[1]-trL)/(n*(n-1.0));
    double mHSIC = (1.0 + muX*muY - muX - muY)/n;
    double a = mHSIC*mHSIC/varHSIC;
    double bet = varHSIC*n/mHSIC;

    // S_k = sum_{j=1..k} ln(a+j), k = 0..4095 (block prefix scan)
    double lg[4];
    #pragma unroll
    for (int q=0;q<4;q++) lg[q] = log(a + (double)(4*t+q+1));
    double part = lg[0]+lg[1]+lg[2]+lg[3];
    shD[t]=part; __syncthreads();
    for (int off=1; off<1024; off<<=1){
        double v = (t>=off) ? shD[t-off] : 0.0;
        __syncthreads(); shD[t]+=v; __syncthreads();
    }
    double excl = shD[t]-part;
    S[4*t]   = excl;
    S[4*t+1] = excl+lg[0];
    S[4*t+2] = excl+lg[0]+lg[1];
    S[4*t+3] = excl+lg[0]+lg[1]+lg[2];
    __syncthreads();

    double lga1 = lgamma(a+1.0);
    const double p = 0.2;                       // 1 - ALPH
    double z = -0.8416212335729143;             // Phi^-1(0.2)
    double u = 1.0 - 1.0/(9.0*a) + z/(3.0*sqrt(a));
    double x = a*u*u*u;
    if (!(x > 1e-8)) x = 0.5*a + 1e-3;
    for (int it=0; it<5; it++){
        double lnx = log(x);
        double b0 = a*lnx - x - lga1;
        double loc = 0.0;
        #pragma unroll
        for (int q=0;q<4;q++){
            int k = 4*t+q;
            double e = b0 + (double)k*lnx - S[k];
            if (e > -740.0) loc += exp(e);
        }
        double P = blockReduceD(loc, shD);
        double lpdf = (a-1.0)*lnx - x - (lga1 - log(a));
        double pdf = exp(lpdf);
        if (pdf < 1e-300) pdf = 1e-300;
        double xn = x - (P - p)/pdf;
        if (!(xn > 0.5*x)) xn = 0.5*x;
        if (xn > 2.0*x) xn = 2.0*x;
        x = xn;
    }
    if (t==0){
        out[0] = (float)testStat;
        out[1] = (float)(bet*x);
    }
}

// ----------------------------------------------------------------------------
extern "C" void kernel_launch(void* const* d_in, const int* in_sizes, int n_in,
                              void* d_out, int out_size) {
    const float* X = (const float*)d_in[0];
    const float* Y = (const float*)d_in[1];
    float* out = (float*)d_out;
    (void)in_sizes; (void)n_in; (void)out_size;

    k_initA<<<1024, 256>>>();
    k_normsX<<<512, 256>>>(X);
    k_normsY<<<512, 256>>>(Y);
    k_dist<<<dim3(TILES,2), 256>>>(X, Y);        // profile slot 4
    k_sel1<<<1, 1024>>>();
    k_hist2<<<dim3(TILES,2), 256>>>();
    k_sel2<<<1, 1024>>>();
    k_rowsum<<<dim3(TILES,2), 256>>>();
    k_prep<<<1, 1024>>>();
    k_main<<<TILES, 256>>>();
    k_final<<<1, 1024>>>(out);
}

// round 7
// speedup vs baseline: 1.7794x; 1.7794x over previous
#include <cuda_runtime.h>
#include <math.h>
#include <stdint.h>

#define Nn    4096
#define DIMS  64
#define NNt   (Nn*Nn)
#define NB1   1024
#define SH1   16
#define NB2   131072           /* two 65536-key exact regions */
#define KB    0xC0800000u      /* f2k(4.0f) */
#define SPAN1 0x04000000u      /* 2^26 keys: values [4,1024) */
/* ranks (0-indexed, ascending) of the two triu-median values in the FULL
   n^2 multiset: triu ranks m/2-1, m/2 (m=n(n-1)/2) each doubled, plus
   4096 diagonal (~0) entries below everything */
#define R_LO 8390655u
#define R_HI 8390656u
#define TNT   32               /* tile grid dim: 4096/128 */
#define TILES 528              /* upper-tri tiles incl diagonal */

// ------------- device scratch (globals: no allocations allowed) -------------
__device__ float    g_D[2][NNt];
__device__ float    g_G[2][Nn];
__device__ unsigned g_hist1[2][NB1];
__device__ unsigned g_below1[2];
__device__ unsigned g_W1[2], g_W2[2];
__device__ unsigned g_hist2[2][NB2];
__device__ unsigned g_below2[2];
__device__ float    g_c[2];          // -log2(e)/median
__device__ double   g_rowd[2][Nn];
__device__ float    g_rmf[2][Nn];
__device__ float    g_tmf[2];
__device__ double   g_totd[2];
__device__ double   g_part[5][TILES];

__device__ __forceinline__ unsigned f2k(float f){
    unsigned u = __float_as_uint(f);
    return (u & 0x80000000u) ? ~u : (u | 0x80000000u);
}
__device__ __forceinline__ float k2f(unsigned k){
    unsigned u = (k & 0x80000000u) ? (k & 0x7FFFFFFFu) : ~k;
    return __uint_as_float(u);
}
// decode linear upper-triangle tile index -> (bi,bj), bi<=bj
__device__ __forceinline__ void tri_decode(int q, int &bi, int &bj){
    int b = (int)((65.0 - sqrt(65.0*65.0 - 8.0*(double)q))*0.5);
    if (b > TNT-1) b = TNT-1;
    while (b*(2*TNT+1-b)/2 > q) b--;
    while ((b+1)*(2*TNT+1-(b+1))/2 <= q) b++;
    bi = b; bj = b + (q - b*(2*TNT+1-b)/2);
}

// --------------- init: zero state + squared norms (merged) ------------------
__global__ void k_init(const float* __restrict__ X, const float* __restrict__ Y){
    int idx = blockIdx.x*256 + threadIdx.x;          // 0 .. 262143
    if (idx < 2*NB1) ((unsigned*)g_hist1)[idx] = 0u;
    if (idx < 2*NB2) ((unsigned*)g_hist2)[idx] = 0u;
    if (idx < 2){ g_below1[idx]=0u; g_below2[idx]=0u; }
    if (idx < 2*Nn) ((double*)g_rowd)[idx] = 0.0;
    {   // one warp per row: 2*4096 rows * 32 lanes = 262144 threads exactly
        int w = idx >> 5;
        int lane = idx & 31;
        const float* A = (w & 4096) ? Y : X;
        int row = w & 4095;
        float a = A[row*DIMS + lane];
        float b = A[row*DIMS + lane + 32];
        float s = a*a + b*b;
        #pragma unroll
        for (int off=16; off; off>>=1) s += __shfl_xor_sync(0xffffffffu, s, off);
        if (lane==0) g_G[w>>12][row] = s;
    }
}

// ---- upper-tri distance tiles: D = Gi+Gj-2*dot (8x8 reg tile + fused hist) --
__global__ void __launch_bounds__(256) k_dist(const float* __restrict__ X,
                                              const float* __restrict__ Y){
    const int mat = blockIdx.y;
    const float* A = mat ? Y : X;
    float* D = g_D[mat];
    const float* G = g_G[mat];
    int bi, bj; tri_decode(blockIdx.x, bi, bj);
    int i0 = bi*128, j0 = bj*128;
    __shared__ float As[128][33];
    __shared__ float Bs[128][33];
    __shared__ unsigned hb[NB1+1];    // [NB1] = below-4.0 counter
    int t = threadIdx.x;
    int tx = t & 15, ty = t >> 4;
    for (int b=t; b<NB1+1; b+=256) hb[b]=0u;

    float acc[8][8];
    #pragma unroll
    for (int a=0;a<8;a++)
        #pragma unroll
        for (int b=0;b<8;b++) acc[a][b]=0.0f;

    for (int kk=0; kk<64; kk+=32){
        __syncthreads();
        #pragma unroll
        for (int it=0; it<4; it++){
            int l = t + it*256;          // 0..1023 float4 slots
            int r = l >> 3, c4 = l & 7;
            float4 va = *(const float4*)&A[(i0+r)*DIMS + kk + c4*4];
            As[r][c4*4+0]=va.x; As[r][c4*4+1]=va.y; As[r][c4*4+2]=va.z; As[r][c4*4+3]=va.w;
            float4 vb = *(const float4*)&A[(j0+r)*DIMS + kk + c4*4];
            Bs[r][c4*4+0]=vb.x; Bs[r][c4*4+1]=vb.y; Bs[r][c4*4+2]=vb.z; Bs[r][c4*4+3]=vb.w;
        }
        __syncthreads();
        #pragma unroll 8
        for (int k=0;k<32;k++){
            float ar[8], br[8];
            #pragma unroll
            for (int a=0;a<8;a++) ar[a] = As[ty+16*a][k];
            #pragma unroll
            for (int b=0;b<8;b++) br[b] = Bs[tx+16*b][k];
            #pragma unroll
            for (int a=0;a<8;a++)
                #pragma unroll
                for (int b=0;b<8;b++) acc[a][b] += ar[a]*br[b];
        }
    }

    unsigned w = (bi==bj) ? 1u : 2u;
    float gi[8], gj[8];
    #pragma unroll
    for (int a=0;a<8;a++) gi[a] = G[i0+ty+16*a];
    #pragma unroll
    for (int b=0;b<8;b++) gj[b] = G[j0+tx+16*b];
    #pragma unroll
    for (int a=0;a<8;a++){
        int i = i0 + ty + 16*a;
        #pragma unroll
        for (int b=0;b<8;b++){
            int j = j0 + tx + 16*b;
            float v = gi[a] + gj[b] - 2.0f*acc[a][b];
            D[(size_t)i*Nn + j] = v;
            unsigned key = f2k(v);
            unsigned off = key - KB;
            if (off < SPAN1) atomicAdd(&hb[off>>SH1], w);
            else if (key < KB) atomicAdd(&hb[NB1], w);
        }
    }
    __syncthreads();
    for (int b=t; b<NB1; b+=256)
        if (hb[b]) atomicAdd(&g_hist1[mat][b], hb[b]);
    if (t==0 && hb[NB1]) atomicAdd(&g_below1[mat], hb[NB1]);
}

// --------- locate the (<=2) coarse bins holding ranks R_LO / R_HI -----------
__global__ void k_sel1(){
    __shared__ unsigned sh[NB1];
    __shared__ int sb1, sb2;
    int t = threadIdx.x;
    for (int m=0;m<2;m++){
        if (t==0){ sb1=-1; sb2=-1; }
        unsigned c = g_hist1[m][t];
        sh[t]=c; __syncthreads();
        for (int off=1; off<NB1; off<<=1){
            unsigned v = (t>=off) ? sh[t-off] : 0u;
            __syncthreads(); sh[t]+=v; __syncthreads();
        }
        unsigned lo = g_below1[m] + (sh[t]-c);
        unsigned hi = lo + c;
        if (c){
            if (lo<=R_LO && R_LO<hi) sb1 = t;
            if (lo<=R_HI && R_HI<hi) sb2 = t;
        }
        __syncthreads();
        if (t==0){
            int b1=sb1, b2=sb2;
            if (b1<0) b1 = (b2>=0)? b2 : NB1/2;
            if (b2<0) b2 = b1;
            if (b2==b1) b2 = b1+1;                   // keep regions disjoint
            g_W1[m] = KB + ((unsigned)b1 << SH1);
            g_W2[m] = KB + ((unsigned)b2 << SH1);
        }
        __syncthreads();
    }
}

// ----- exact pass over upper tiles: per-key hist in 2 regions (weighted) ----
__global__ void k_hist2(){
    int mat = blockIdx.y;
    int bi, bj; tri_decode(blockIdx.x, bi, bj);
    int i0 = bi*128, j0 = bj*128;
    unsigned w = (bi==bj) ? 1u : 2u;
    unsigned W1 = g_W1[mat], W2 = g_W2[mat];
    int warp = threadIdx.x >> 5, lane = threadIdx.x & 31;
    unsigned below = 0;
    for (int r = warp; r < 128; r += 8){
        float4 d = *(const float4*)&g_D[mat][(size_t)(i0+r)*Nn + j0 + lane*4];
        #pragma unroll
        for (int c=0;c<4;c++){
            float val = (c==0)?d.x:(c==1)?d.y:(c==2)?d.z:d.w;
            unsigned key = f2k(val);
            unsigned o1 = key - W1;
            if (o1 < 65536u) atomicAdd(&g_hist2[mat][o1], w);
            else {
                unsigned o2 = key - W2;
                if (o2 < 65536u) atomicAdd(&g_hist2[mat][65536u+o2], w);
                else if (key < W1) below += w;
            }
        }
    }
    #pragma unroll
    for (int off=16; off; off>>=1) below += __shfl_xor_sync(0xffffffffu, below, off);
    __shared__ unsigned sb[8];
    if (lane==0) sb[warp]=below;
    __syncthreads();
    if (threadIdx.x==0){
        unsigned s=0;
        for (int q=0;q<8;q++) s+=sb[q];
        if (s) atomicAdd(&g_below2[mat], s);
    }
}

// -- exact median keys via two-phase coalesced select (chunk sums + drill) ---
__global__ void k_sel2(){
    __shared__ unsigned C[1024];      // chunk sums (128 bins each)
    __shared__ unsigned P[1024];      // inclusive prefix of C
    __shared__ int sq1, sq2;
    __shared__ unsigned sr1, sr2;     // exclusive rank at chunk start
    __shared__ unsigned keys[2];
    int t = threadIdx.x;
    int warp = t >> 5, lane = t & 31;
    for (int m=0;m<2;m++){
        // phase 1: coalesced chunk sums (warp w handles chunks w*32..w*32+31)
        for (int cq=0; cq<32; cq++){
            int q = warp*32 + cq;
            const unsigned* base = &g_hist2[m][q*128];
            unsigned s = base[lane] + base[lane+32] + base[lane+64] + base[lane+96];
            #pragma unroll
            for (int off=16; off; off>>=1) s += __shfl_xor_sync(0xffffffffu, s, off);
            if (lane==0) C[q] = s;
        }
        __syncthreads();
        // phase 2: scan chunk sums, locate chunks holding R_LO / R_HI
        if (t==0){ sq1=-1; sq2=-1; sr1=0u; sr2=0u; }
        unsigned c = C[t];
        P[t]=c; __syncthreads();
        for (int off=1; off<1024; off<<=1){
            unsigned v = (t>=off) ? P[t-off] : 0u;
            __syncthreads(); P[t]+=v; __syncthreads();
        }
        unsigned lo = g_below2[m] + (P[t]-c);
        unsigned hi = lo + c;
        if (c){
            if (lo<=R_LO && R_LO<hi){ sq1 = t; sr1 = lo; }
            if (lo<=R_HI && R_HI<hi){ sq2 = t; sr2 = lo; }
        }
        __syncthreads();
        // phase 3: serial drill-down inside the target chunks (L1/L2-hot)
        if (t==0){
            int o1=-1, o2=-1;
            if (sq1>=0){
                unsigned run = sr1;
                for (int b=0;b<128;b++){
                    unsigned cnt = g_hist2[m][sq1*128+b];
                    if (run<=R_LO && R_LO<run+cnt){ o1 = sq1*128+b; break; }
                    run += cnt;
                }
            }
            if (sq2>=0){
                unsigned run = sr2;
                for (int b=0;b<128;b++){
                    unsigned cnt = g_hist2[m][sq2*128+b];
                    if (run<=R_HI && R_HI<run+cnt){ o2 = sq2*128+b; break; }
                    run += cnt;
                }
            }
            if (o1<0 && o2>=0) o1=o2;
            if (o2<0 && o1>=0) o2=o1;
            if (o1<0){ o1=32768; o2=32768; }         // unreachable safety
            unsigned W1=g_W1[m], W2=g_W2[m];
            keys[0] = (o1<65536)? W1+(unsigned)o1 : W2+(unsigned)(o1-65536);
            keys[1] = (o2<65536)? W1+(unsigned)o2 : W2+(unsigned)(o2-65536);
            float med = 0.5f*(k2f(keys[0])+k2f(keys[1]));  // median == 2*width^2
            g_c[m] = -(float)(1.4426950408889634 / (double)med);
        }
        __syncthreads();
    }
}

// ----- row sums from upper tiles: row partials + transposed col partials ----
__global__ void k_rowsum(){
    int mat = blockIdx.y;
    int bi, bj; tri_decode(blockIdx.x, bi, bj);
    int i0 = bi*128, j0 = bj*128;
    float c = g_c[mat];
    int warp = threadIdx.x >> 5, lane = threadIdx.x & 31;
    float ca0=0.f, ca1=0.f, ca2=0.f, ca3=0.f;
    for (int r = warp; r < 128; r += 8){
        float4 d = *(const float4*)&g_D[mat][(size_t)(i0+r)*Nn + j0 + lane*4];
        float e0=exp2f(d.x*c), e1=exp2f(d.y*c), e2=exp2f(d.z*c), e3=exp2f(d.w*c);
        float rs = (e0+e1)+(e2+e3);
        #pragma unroll
        for (int off=16; off; off>>=1) rs += __shfl_xor_sync(0xffffffffu, rs, off);
        if (lane==0) atomicAdd(&g_rowd[mat][i0+r], (double)rs);
        ca0+=e0; ca1+=e1; ca2+=e2; ca3+=e3;
    }
    if (bi != bj){
        __shared__ float cs[8][128];
        cs[warp][lane*4+0]=ca0; cs[warp][lane*4+1]=ca1;
        cs[warp][lane*4+2]=ca2; cs[warp][lane*4+3]=ca3;
        __syncthreads();
        if (threadIdx.x < 128){
            float s=0.f;
            #pragma unroll
            for (int q=0;q<8;q++) s += cs[q][threadIdx.x];
            atomicAdd(&g_rowd[mat][j0+threadIdx.x], (double)s);
        }
    }
}

__device__ double blockReduceD(double v, double* sh){
    int t = threadIdx.x;
    sh[t]=v; __syncthreads();
    for (int off=512; off; off>>=1){
        if (t<off) sh[t]+=sh[t+off];
        __syncthreads();
    }
    double r = sh[0]; __syncthreads();
    return r;
}

// --------------------- totals + means from row sums -------------------------
__global__ void k_prep(){
    __shared__ double shD[1024];
    int t = threadIdx.x;
    for (int m=0;m<2;m++){
        double s=0.0;
        for (int k=t;k<Nn;k+=1024) s += g_rowd[m][k];
        double tot = blockReduceD(s, shD);
        if (t==0){ g_totd[m]=tot; g_tmf[m]=(float)(tot/((double)Nn*(double)Nn)); }
    }
    for (int k=t;k<2*Nn;k+=1024){
        int m=k>>12, i=k&4095;
        g_rmf[m][i] = (float)(g_rowd[m][i]*(1.0/(double)Nn));
    }
}

// -- fused centered-product over upper tiles (S1,S2 weighted; diag extras) ---
__global__ void k_main(){
    int bi, bj; tri_decode(blockIdx.x, bi, bj);
    int i0 = bi*128, j0 = bj*128;
    bool diag = (bi==bj);
    float cX=g_c[0], cY=g_c[1];
    float tmK=g_tmf[0], tmL=g_tmf[1];
    int warp = threadIdx.x >> 5, lane = threadIdx.x & 31;
    float4 rmKj = *(const float4*)&g_rmf[0][j0 + lane*4];
    float4 rmLj = *(const float4*)&g_rmf[1][j0 + lane*4];
    float s1=0.f, s2=0.f, s2d=0.f, trk=0.f, trl=0.f;
    for (int r = warp; r < 128; r += 8){
        int i = i0 + r;
        float rmKi = __ldg(&g_rmf[0][i]);
        float rmLi = __ldg(&g_rmf[1][i]);
        float4 dx = *(const float4*)&g_D[0][(size_t)i*Nn + j0 + lane*4];
        float4 dy = *(const float4*)&g_D[1][(size_t)i*Nn + j0 + lane*4];
        #pragma unroll
        for (int c=0;c<4;c++){
            float dxx = (c==0)?dx.x:(c==1)?dx.y:(c==2)?dx.z:dx.w;
            float dyy = (c==0)?dy.x:(c==1)?dy.y:(c==2)?dy.z:dy.w;
            float rkj = (c==0)?rmKj.x:(c==1)?rmKj.y:(c==2)?rmKj.z:rmKj.w;
            float rlj = (c==0)?rmLj.x:(c==1)?rmLj.y:(c==2)?rmLj.z:rmLj.w;
            float k = exp2f(dxx*cX);
            float l = exp2f(dyy*cY);
            float kc = k - rmKi - rkj + tmK;
            float lc = l - rmLi - rlj + tmL;
            float pr = kc*lc;
            s1 += pr;
            float p6 = pr*(1.0f/6.0f);
            float p66 = p6*p6;
            s2 += p66;
            if (diag && r == lane*4+c){ s2d += p66; trk += k; trl += l; }
        }
    }
    double wgt = diag ? 1.0 : 2.0;
    __shared__ double sd[256];
    double vals[5] = {wgt*(double)s1, wgt*(double)s2, (double)s2d, (double)trk, (double)trl};
    for (int q=0;q<5;q++){
        sd[threadIdx.x]=vals[q]; __syncthreads();
        for (int off=128; off; off>>=1){
            if (threadIdx.x<off) sd[threadIdx.x]+=sd[threadIdx.x+off];
            __syncthreads();
        }
        if (threadIdx.x==0) g_part[q][blockIdx.x]=sd[0];
        __syncthreads();
    }
}

// --------- final scalars + gamma quantile (parallel-series Newton) ----------
__global__ void k_final(float* out){
    __shared__ double shD[1024];
    __shared__ double S[4096];
    int t = threadIdx.x;
    double red[5];
    for (int q=0;q<5;q++){
        double s=0.0;
        for (int k=t;k<TILES;k+=1024) s += g_part[q][k];
        red[q] = blockReduceD(s, shD);
    }
    const double n = (double)Nn;
    double S1=red[0], S2=red[1], S2d=red[2], trK=red[3], trL=red[4];
    double testStat = S1/n;
    double varHSIC = (S2 - S2d)/(n*(n-1.0));
    varHSIC = varHSIC * 72.0*(n-4.0)*(n-5.0)/(n*(n-1.0)*(n-2.0)*(n-3.0));
    double muX = (g_totd[0]-trK)/(n*(n-1.0));
    double muY = (g_totd[1]-trL)/(n*(n-1.0));
    double mHSIC = (1.0 + muX*muY - muX - muY)/n;
    double a = mHSIC*mHSIC/varHSIC;
    double bet = varHSIC*n/mHSIC;

    // S_k = sum_{j=1..k} ln(a+j), k = 0..4095 (block prefix scan)
    double lg[4];
    #pragma unroll
    for (int q=0;q<4;q++) lg[q] = log(a + (double)(4*t+q+1));
    double part = lg[0]+lg[1]+lg[2]+lg[3];
    shD[t]=part; __syncthreads();
    for (int off=1; off<1024; off<<=1){
        double v = (t>=off) ? shD[t-off] : 0.0;
        __syncthreads(); shD[t]+=v; __syncthreads();
    }
    double excl = shD[t]-part;
    S[4*t]   = excl;
    S[4*t+1] = excl+lg[0];
    S[4*t+2] = excl+lg[0]+lg[1];
    S[4*t+3] = excl+lg[0]+lg[1]+lg[2];
    __syncthreads();

    double lga1 = lgamma(a+1.0);
    const double p = 0.2;                       // 1 - ALPH
    double z = -0.8416212335729143;             // Phi^-1(0.2)
    double u = 1.0 - 1.0/(9.0*a) + z/(3.0*sqrt(a));
    double x = a*u*u*u;
    if (!(x > 1e-8)) x = 0.5*a + 1e-3;
    for (int it=0; it<4; it++){
        double lnx = log(x);
        double b0 = a*lnx - x - lga1;
        double loc = 0.0;
        #pragma unroll
        for (int q=0;q<4;q++){
            int k = 4*t+q;
            double e = b0 + (double)k*lnx - S[k];
            if (e > -45.0) loc += exp(e);
        }
        double P = blockReduceD(loc, shD);
        double lpdf = (a-1.0)*lnx - x - (lga1 - log(a));
        double pdf = exp(lpdf);
        if (pdf < 1e-300) pdf = 1e-300;
        double xn = x - (P - p)/pdf;
        if (!(xn > 0.5*x)) xn = 0.5*x;
        if (xn > 2.0*x) xn = 2.0*x;
        x = xn;
    }
    if (t==0){
        out[0] = (float)testStat;
        out[1] = (float)(bet*x);
    }
}

// ----------------------------------------------------------------------------
extern "C" void kernel_launch(void* const* d_in, const int* in_sizes, int n_in,
                              void* d_out, int out_size) {
    const float* X = (const float*)d_in[0];
    const float* Y = (const float*)d_in[1];
    float* out = (float*)d_out;
    (void)in_sizes; (void)n_in; (void)out_size;

    k_init<<<1024, 256>>>(X, Y);
    k_dist<<<dim3(TILES,2), 256>>>(X, Y);
    k_sel1<<<1, 1024>>>();
    k_hist2<<<dim3(TILES,2), 256>>>();           // profile slot 3 (control)
    k_sel2<<<1, 1024>>>();
    k_rowsum<<<dim3(TILES,2), 256>>>();
    k_prep<<<1, 1024>>>();
    k_main<<<TILES, 256>>>();
    k_final<<<1, 1024>>>(out);
}

// round 8
// speedup vs baseline: 2.0362x; 1.1443x over previous
#include <cuda_runtime.h>
#include <math.h>
#include <stdint.h>

#define Nn    4096
#define DIMS  64
#define NB1   1024
#define SH1   16
#define NB2   131072           /* two 65536-key exact regions */
#define KB    0xC0800000u      /* f2k(4.0f) */
#define SPAN1 0x04000000u      /* 2^26 keys: values [4,1024) */
/* ranks (0-indexed, ascending) of the two triu-median values in the FULL
   n^2 multiset: triu ranks m/2-1, m/2 (m=n(n-1)/2) each doubled, plus
   4096 diagonal (~0) entries below everything */
#define R_LO 8390655u
#define R_HI 8390656u
#define TNT   32               /* tile grid dim: 4096/128 */
#define TILES 528              /* upper-tri tiles incl diagonal */
#define TSZ   16384            /* floats per 128x128 tile */

// ------------- device scratch (globals: no allocations allowed) -------------
__device__ float    g_D[2][TILES*TSZ];   // TILED layout: tile q contiguous
__device__ float    g_G[2][Nn];
__device__ unsigned g_hist1[2][NB1];
__device__ unsigned g_below1[2];
__device__ unsigned g_hist2[2][NB2];
__device__ unsigned g_below2[2];
__device__ float    g_c[2];          // -log2(e)/median
__device__ double   g_rowd[2][Nn];
__device__ double   g_part[5][TILES];

__device__ __forceinline__ unsigned f2k(float f){
    unsigned u = __float_as_uint(f);
    return (u & 0x80000000u) ? ~u : (u | 0x80000000u);
}
__device__ __forceinline__ float k2f(unsigned k){
    unsigned u = (k & 0x80000000u) ? (k & 0x7FFFFFFFu) : ~k;
    return __uint_as_float(u);
}
// decode linear upper-triangle tile index -> (bi,bj), bi<=bj
__device__ __forceinline__ void tri_decode(int q, int &bi, int &bj){
    int b = (int)((65.0 - sqrt(65.0*65.0 - 8.0*(double)q))*0.5);
    if (b > TNT-1) b = TNT-1;
    while (b*(2*TNT+1-b)/2 > q) b--;
    while ((b+1)*(2*TNT+1-(b+1))/2 <= q) b++;
    bi = b; bj = b + (q - b*(2*TNT+1-b)/2);
}

// --------------- init: zero state + squared norms (merged) ------------------
__global__ void k_init(const float* __restrict__ X, const float* __restrict__ Y){
    int idx = blockIdx.x*256 + threadIdx.x;          // 0 .. 262143
    if (idx < 2*NB1) ((unsigned*)g_hist1)[idx] = 0u;
    if (idx < 2*NB2) ((unsigned*)g_hist2)[idx] = 0u;
    if (idx < 2){ g_below1[idx]=0u; g_below2[idx]=0u; }
    if (idx < 2*Nn) ((double*)g_rowd)[idx] = 0.0;
    {   // one warp per row: 2*4096 rows * 32 lanes = 262144 threads exactly
        int w = idx >> 5;
        int lane = idx & 31;
        const float* A = (w & 4096) ? Y : X;
        int row = w & 4095;
        float a = A[row*DIMS + lane];
        float b = A[row*DIMS + lane + 32];
        float s = a*a + b*b;
        #pragma unroll
        for (int off=16; off; off>>=1) s += __shfl_xor_sync(0xffffffffu, s, off);
        if (lane==0) g_G[w>>12][row] = s;
    }
}

// ---- upper-tri distance tiles: D = Gi+Gj-2*dot (8x8 reg tile + fused hist) --
__global__ void __launch_bounds__(256) k_dist(const float* __restrict__ X,
                                              const float* __restrict__ Y){
    const int mat = blockIdx.y;
    const float* A = mat ? Y : X;
    float* Dt = g_D[mat] + (size_t)blockIdx.x * TSZ;
    const float* G = g_G[mat];
    int bi, bj; tri_decode(blockIdx.x, bi, bj);
    int i0 = bi*128, j0 = bj*128;
    __shared__ float As[128][33];
    __shared__ float Bs[128][33];
    __shared__ unsigned hb[NB1+1];    // [NB1] = below-4.0 counter
    int t = threadIdx.x;
    int tx = t & 15, ty = t >> 4;
    for (int b=t; b<NB1+1; b+=256) hb[b]=0u;

    float acc[8][8];
    #pragma unroll
    for (int a=0;a<8;a++)
        #pragma unroll
        for (int b=0;b<8;b++) acc[a][b]=0.0f;

    for (int kk=0; kk<64; kk+=32){
        __syncthreads();
        #pragma unroll
        for (int it=0; it<4; it++){
            int l = t + it*256;          // 0..1023 float4 slots
            int r = l >> 3, c4 = l & 7;
            float4 va = *(const float4*)&A[(i0+r)*DIMS + kk + c4*4];
            As[r][c4*4+0]=va.x; As[r][c4*4+1]=va.y; As[r][c4*4+2]=va.z; As[r][c4*4+3]=va.w;
            float4 vb = *(const float4*)&A[(j0+r)*DIMS + kk + c4*4];
            Bs[r][c4*4+0]=vb.x; Bs[r][c4*4+1]=vb.y; Bs[r][c4*4+2]=vb.z; Bs[r][c4*4+3]=vb.w;
        }
        __syncthreads();
        #pragma unroll 8
        for (int k=0;k<32;k++){
            float ar[8], br[8];
            #pragma unroll
            for (int a=0;a<8;a++) ar[a] = As[ty+16*a][k];
            #pragma unroll
            for (int b=0;b<8;b++) br[b] = Bs[tx+16*b][k];
            #pragma unroll
            for (int a=0;a<8;a++)
                #pragma unroll
                for (int b=0;b<8;b++) acc[a][b] += ar[a]*br[b];
        }
    }

    unsigned w = (bi==bj) ? 1u : 2u;
    float gi[8], gj[8];
    #pragma unroll
    for (int a=0;a<8;a++) gi[a] = G[i0+ty+16*a];
    #pragma unroll
    for (int b=0;b<8;b++) gj[b] = G[j0+tx+16*b];
    #pragma unroll
    for (int a=0;a<8;a++){
        #pragma unroll
        for (int b=0;b<8;b++){
            float v = gi[a] + gj[b] - 2.0f*acc[a][b];
            Dt[(ty+16*a)*128 + tx+16*b] = v;
            unsigned key = f2k(v);
            unsigned off = key - KB;
            if (off < SPAN1) atomicAdd(&hb[off>>SH1], w);
            else if (key < KB) atomicAdd(&hb[NB1], w);
        }
    }
    __syncthreads();
    for (int b=t; b<NB1; b+=256)
        if (hb[b]) atomicAdd(&g_hist1[mat][b], hb[b]);
    if (t==0 && hb[NB1]) atomicAdd(&g_below1[mat], hb[NB1]);
}

// ---- per-block window derivation from hist1 (256 threads, deterministic) ---
__device__ void find_windows256(int mat, unsigned &W1, unsigned &W2,
                                unsigned* shScan, int* shB){
    int t = threadIdx.x;
    if (t==0){ shB[0]=-1; shB[1]=-1; }
    unsigned c0[4]; unsigned local=0;
    #pragma unroll
    for (int q=0;q<4;q++){ c0[q]=g_hist1[mat][t*4+q]; local+=c0[q]; }
    shScan[t]=local; __syncthreads();
    for (int off=1; off<256; off<<=1){
        unsigned v = (t>=off)? shScan[t-off] : 0u;
        __syncthreads(); shScan[t]+=v; __syncthreads();
    }
    unsigned run = g_below1[mat] + (shScan[t]-local);
    #pragma unroll
    for (int q=0;q<4;q++){
        unsigned lo=run, hi=run+c0[q];
        if (c0[q]){
            if (lo<=R_LO && R_LO<hi) shB[0]=t*4+q;
            if (lo<=R_HI && R_HI<hi) shB[1]=t*4+q;
        }
        run=hi;
    }
    __syncthreads();
    int b1=shB[0], b2=shB[1];
    if (b1<0) b1 = (b2>=0)? b2 : NB1/2;
    if (b2<0) b2 = b1;
    if (b2==b1) b2 = b1+1;                        // keep regions disjoint
    W1 = KB + ((unsigned)b1 << SH1);
    W2 = KB + ((unsigned)b2 << SH1);
    __syncthreads();
}

// ----- exact pass over upper tiles: per-key hist in 2 regions (weighted) ----
__global__ void k_hist2(){
    int mat = blockIdx.y;
    __shared__ unsigned shScan[256];
    __shared__ int shB[2];
    unsigned W1, W2;
    find_windows256(mat, W1, W2, shScan, shB);

    int bi, bj; tri_decode(blockIdx.x, bi, bj);
    unsigned w = (bi==bj) ? 1u : 2u;
    const float* Dt = g_D[mat] + (size_t)blockIdx.x * TSZ;
    int warp = threadIdx.x >> 5, lane = threadIdx.x & 31;
    unsigned below = 0;
    #pragma unroll 2
    for (int it=0; it<8; it++){
        int r = warp + it*16;
        float4 d1 = *(const float4*)&Dt[r*128 + lane*4];
        float4 d2 = *(const float4*)&Dt[(r+8)*128 + lane*4];
        #pragma unroll
        for (int half=0; half<2; half++){
            float4 d = half ? d2 : d1;
            #pragma unroll
            for (int c=0;c<4;c++){
                float val = (c==0)?d.x:(c==1)?d.y:(c==2)?d.z:d.w;
                unsigned key = f2k(val);
                unsigned o1 = key - W1;
                if (o1 < 65536u) atomicAdd(&g_hist2[mat][o1], w);
                else {
                    unsigned o2 = key - W2;
                    if (o2 < 65536u) atomicAdd(&g_hist2[mat][65536u+o2], w);
                    else if (key < W1) below += w;
                }
            }
        }
    }
    #pragma unroll
    for (int off=16; off; off>>=1) below += __shfl_xor_sync(0xffffffffu, below, off);
    __shared__ unsigned sb[8];
    if (lane==0) sb[warp]=below;
    __syncthreads();
    if (threadIdx.x==0){
        unsigned s=0;
        for (int q=0;q<8;q++) s+=sb[q];
        if (s) atomicAdd(&g_below2[mat], s);
    }
}

// -- exact median keys: windows + chunk scan + PARALLEL drill-down -----------
__global__ void k_sel2(){
    __shared__ unsigned sh[1024];
    __shared__ unsigned C[1024];
    __shared__ int sB1, sB2;          // coarse bins
    __shared__ int sq1, sq2;          // target chunks
    __shared__ unsigned sr1, sr2;     // exclusive rank at chunk start
    __shared__ int so1, so2;          // final bin offsets
    int t = threadIdx.x;
    int warp = t >> 5, lane = t & 31;
    for (int m=0;m<2;m++){
        // ---- derive W1/W2 from hist1 (1 bin per thread) ----
        if (t==0){ sB1=-1; sB2=-1; sq1=-1; sq2=-1; so1=-1; so2=-1; }
        __syncthreads();
        unsigned c1 = g_hist1[m][t];
        sh[t]=c1; __syncthreads();
        for (int off=1; off<1024; off<<=1){
            unsigned v=(t>=off)?sh[t-off]:0u;
            __syncthreads(); sh[t]+=v; __syncthreads();
        }
        {
            unsigned lo = g_below1[m] + (sh[t]-c1);
            if (c1){
                if (lo<=R_LO && R_LO<lo+c1) sB1=t;
                if (lo<=R_HI && R_HI<lo+c1) sB2=t;
            }
        }
        __syncthreads();
        int b1=sB1, b2=sB2;
        if (b1<0) b1=(b2>=0)?b2:NB1/2;
        if (b2<0) b2=b1;
        if (b2==b1) b2=b1+1;
        unsigned W1 = KB + ((unsigned)b1<<SH1);
        unsigned W2 = KB + ((unsigned)b2<<SH1);
        // ---- phase 1: coalesced chunk sums (128 bins per chunk) ----
        for (int cq=0; cq<32; cq++){
            int q = warp*32 + cq;
            const unsigned* base = &g_hist2[m][q*128];
            unsigned s = base[lane] + base[lane+32] + base[lane+64] + base[lane+96];
            #pragma unroll
            for (int off=16; off; off>>=1) s += __shfl_xor_sync(0xffffffffu, s, off);
            if (lane==0) C[q] = s;
        }
        __syncthreads();
        // ---- phase 2: scan chunk sums, locate target chunks ----
        unsigned cc = C[t];
        sh[t]=cc; __syncthreads();
        for (int off=1; off<1024; off<<=1){
            unsigned v=(t>=off)?sh[t-off]:0u;
            __syncthreads(); sh[t]+=v; __syncthreads();
        }
        {
            unsigned lo = g_below2[m] + (sh[t]-cc);
            unsigned hi = lo + cc;
            if (cc){
                if (lo<=R_LO && R_LO<hi){ sq1=t; sr1=lo; }
                if (lo<=R_HI && R_HI<hi){ sq2=t; sr2=lo; }
            }
        }
        __syncthreads();
        // ---- phase 3: PARALLEL drill inside target chunks (128-thread scan) --
        for (int which=0; which<2; which++){
            int sq = which ? sq2 : sq1;
            unsigned sr = which ? sr2 : sr1;
            unsigned RR = which ? R_HI : R_LO;
            if (sq >= 0){
                unsigned cnt = (t<128) ? g_hist2[m][sq*128+t] : 0u;
                sh[t]=cnt; __syncthreads();
                for (int off=1; off<128; off<<=1){
                    unsigned v = (t>=off && t<128)? sh[t-off]:0u;
                    __syncthreads(); if (t<128) sh[t]+=v; __syncthreads();
                }
                if (t<128 && cnt){
                    unsigned lo = sr + (sh[t]-cnt);
                    if (lo<=RR && RR<lo+cnt){
                        if (which) so2 = sq*128+t; else so1 = sq*128+t;
                    }
                }
                __syncthreads();
            }
        }
        if (t==0){
            int o1=so1, o2=so2;
            if (o1<0 && o2>=0) o1=o2;
            if (o2<0 && o1>=0) o2=o1;
            if (o1<0){ o1=32768; o2=32768; }         // unreachable safety
            unsigned k1 = (o1<65536)? W1+(unsigned)o1 : W2+(unsigned)(o1-65536);
            unsigned k2 = (o2<65536)? W1+(unsigned)o2 : W2+(unsigned)(o2-65536);
            float med = 0.5f*(k2f(k1)+k2f(k2));      // median == 2*width^2
            g_c[m] = -(float)(1.4426950408889634 / (double)med);
        }
        __syncthreads();
    }
}

// ----- row sums from upper tiles: row partials + transposed col partials ----
__global__ void k_rowsum(){
    int mat = blockIdx.y;
    int bi, bj; tri_decode(blockIdx.x, bi, bj);
    int i0 = bi*128, j0 = bj*128;
    float c = g_c[mat];
    const float* Dt = g_D[mat] + (size_t)blockIdx.x * TSZ;
    int warp = threadIdx.x >> 5, lane = threadIdx.x & 31;
    float ca0=0.f, ca1=0.f, ca2=0.f, ca3=0.f;
    #pragma unroll 2
    for (int it=0; it<8; it++){
        int r = warp + it*16;
        float4 d1 = *(const float4*)&Dt[r*128 + lane*4];
        float4 d2 = *(const float4*)&Dt[(r+8)*128 + lane*4];
        float a0=exp2f(d1.x*c), a1=exp2f(d1.y*c), a2=exp2f(d1.z*c), a3=exp2f(d1.w*c);
        float b0=exp2f(d2.x*c), b1=exp2f(d2.y*c), b2=exp2f(d2.z*c), b3=exp2f(d2.w*c);
        float rs1 = (a0+a1)+(a2+a3);
        float rs2 = (b0+b1)+(b2+b3);
        #pragma unroll
        for (int off=16; off; off>>=1){
            rs1 += __shfl_xor_sync(0xffffffffu, rs1, off);
            rs2 += __shfl_xor_sync(0xffffffffu, rs2, off);
        }
        if (lane==0){
            atomicAdd(&g_rowd[mat][i0+r],   (double)rs1);
            atomicAdd(&g_rowd[mat][i0+r+8], (double)rs2);
        }
        ca0+=a0+b0; ca1+=a1+b1; ca2+=a2+b2; ca3+=a3+b3;
    }
    if (bi != bj){
        __shared__ float cs[8][128];
        cs[warp][lane*4+0]=ca0; cs[warp][lane*4+1]=ca1;
        cs[warp][lane*4+2]=ca2; cs[warp][lane*4+3]=ca3;
        __syncthreads();
        if (threadIdx.x < 128){
            float s=0.f;
            #pragma unroll
            for (int q=0;q<8;q++) s += cs[q][threadIdx.x];
            atomicAdd(&g_rowd[mat][j0+threadIdx.x], (double)s);
        }
    }
}

__device__ double blockReduce256(double v, double* sh){
    int t = threadIdx.x;
    sh[t]=v; __syncthreads();
    for (int off=128; off; off>>=1){
        if (t<off) sh[t]+=sh[t+off];
        __syncthreads();
    }
    double r = sh[0]; __syncthreads();
    return r;
}
__device__ double blockReduce1024(double v, double* sh){
    int t = threadIdx.x;
    sh[t]=v; __syncthreads();
    for (int off=512; off; off>>=1){
        if (t<off) sh[t]+=sh[t+off];
        __syncthreads();
    }
    double r = sh[0]; __syncthreads();
    return r;
}

// -- fused centered-product over upper tiles (totals recomputed per block) ---
__global__ void k_main(){
    int bi, bj; tri_decode(blockIdx.x, bi, bj);
    int i0 = bi*128, j0 = bj*128;
    bool diag = (bi==bj);
    __shared__ double sd[256];
    int t = threadIdx.x;
    const double invn  = 1.0/(double)Nn;
    const double invn2 = invn*invn;
    // totals (prep merged in): deterministic per-block recompute
    double sK=0.0, sL=0.0;
    for (int k=t;k<Nn;k+=256){ sK += g_rowd[0][k]; sL += g_rowd[1][k]; }
    double totK = blockReduce256(sK, sd);
    double totL = blockReduce256(sL, sd);
    float tmK = (float)(totK*invn2);
    float tmL = (float)(totL*invn2);

    float cX=g_c[0], cY=g_c[1];
    int warp = t >> 5, lane = t & 31;
    float rmKj[4], rmLj[4];
    #pragma unroll
    for (int q=0;q<4;q++){
        rmKj[q] = (float)(__ldg(&g_rowd[0][j0+lane*4+q])*invn);
        rmLj[q] = (float)(__ldg(&g_rowd[1][j0+lane*4+q])*invn);
    }
    const float* DX = g_D[0] + (size_t)blockIdx.x * TSZ;
    const float* DY = g_D[1] + (size_t)blockIdx.x * TSZ;
    float s1=0.f, s2=0.f, s2d=0.f, trk=0.f, trl=0.f;
    #pragma unroll 2
    for (int it=0; it<8; it++){
        int r = warp + it*16;
        float4 dxa = *(const float4*)&DX[r*128 + lane*4];
        float4 dya = *(const float4*)&DY[r*128 + lane*4];
        float4 dxb = *(const float4*)&DX[(r+8)*128 + lane*4];
        float4 dyb = *(const float4*)&DY[(r+8)*128 + lane*4];
        float rmKa = (float)(__ldg(&g_rowd[0][i0+r])*invn);
        float rmLa = (float)(__ldg(&g_rowd[1][i0+r])*invn);
        float rmKb = (float)(__ldg(&g_rowd[0][i0+r+8])*invn);
        float rmLb = (float)(__ldg(&g_rowd[1][i0+r+8])*invn);
        #pragma unroll
        for (int half=0; half<2; half++){
            float4 dx = half?dxb:dxa;
            float4 dy = half?dyb:dya;
            float rmKi = half?rmKb:rmKa;
            float rmLi = half?rmLb:rmLa;
            int rr = r + half*8;
            #pragma unroll
            for (int c=0;c<4;c++){
                float dxx = (c==0)?dx.x:(c==1)?dx.y:(c==2)?dx.z:dx.w;
                float dyy = (c==0)?dy.x:(c==1)?dy.y:(c==2)?dy.z:dy.w;
                float k = exp2f(dxx*cX);
                float l = exp2f(dyy*cY);
                float kc = k - rmKi - rmKj[c] + tmK;
                float lc = l - rmLi - rmLj[c] + tmL;
                float pr = kc*lc;
                s1 += pr;
                float p6 = pr*(1.0f/6.0f);
                float p66 = p6*p6;
                s2 += p66;
                if (diag && rr == lane*4+c){ s2d += p66; trk += k; trl += l; }
            }
        }
    }
    double wgt = diag ? 1.0 : 2.0;
    double vals[5] = {wgt*(double)s1, wgt*(double)s2, (double)s2d, (double)trk, (double)trl};
    for (int q=0;q<5;q++){
        double r = blockReduce256(vals[q], sd);
        if (t==0) g_part[q][blockIdx.x]=r;
    }
}

// --------- final scalars + gamma quantile (parallel-series Newton) ----------
__global__ void k_final(float* out){
    __shared__ double shD[1024];
    __shared__ double S[4096];
    int t = threadIdx.x;
    double red[5];
    for (int q=0;q<5;q++){
        double s=0.0;
        for (int k=t;k<TILES;k+=1024) s += g_part[q][k];
        red[q] = blockReduce1024(s, shD);
    }
    double sK=0.0, sL=0.0;
    for (int k=t;k<Nn;k+=1024){ sK += g_rowd[0][k]; sL += g_rowd[1][k]; }
    double totK = blockReduce1024(sK, shD);
    double totL = blockReduce1024(sL, shD);

    const double n = (double)Nn;
    double S1=red[0], S2=red[1], S2d=red[2], trK=red[3], trL=red[4];
    double testStat = S1/n;
    double varHSIC = (S2 - S2d)/(n*(n-1.0));
    varHSIC = varHSIC * 72.0*(n-4.0)*(n-5.0)/(n*(n-1.0)*(n-2.0)*(n-3.0));
    double muX = (totK-trK)/(n*(n-1.0));
    double muY = (totL-trL)/(n*(n-1.0));
    double mHSIC = (1.0 + muX*muY - muX - muY)/n;
    double a = mHSIC*mHSIC/varHSIC;
    double bet = varHSIC*n/mHSIC;

    // S_k = sum_{j=1..k} ln(a+j), k = 0..4095 (block prefix scan)
    double lg[4];
    #pragma unroll
    for (int q=0;q<4;q++) lg[q] = log(a + (double)(4*t+q+1));
    double part = lg[0]+lg[1]+lg[2]+lg[3];
    shD[t]=part; __syncthreads();
    for (int off=1; off<1024; off<<=1){
        double v = (t>=off) ? shD[t-off] : 0.0;
        __syncthreads(); shD[t]+=v; __syncthreads();
    }
    double excl = shD[t]-part;
    S[4*t]   = excl;
    S[4*t+1] = excl+lg[0];
    S[4*t+2] = excl+lg[0]+lg[1];
    S[4*t+3] = excl+lg[0]+lg[1]+lg[2];
    __syncthreads();

    double lga1 = lgamma(a+1.0);
    const double p = 0.2;                       // 1 - ALPH
    double z = -0.8416212335729143;             // Phi^-1(0.2)
    double u = 1.0 - 1.0/(9.0*a) + z/(3.0*sqrt(a));
    double x = a*u*u*u;
    if (!(x > 1e-8)) x = 0.5*a + 1e-3;
    for (int it=0; it<2; it++){
        double lnx = log(x);
        double b0 = a*lnx - x - lga1;
        double loc = 0.0;
        #pragma unroll
        for (int q=0;q<4;q++){
            int k = 4*t+q;
            double e = b0 + (double)k*lnx - S[k];
            if (e > -45.0) loc += exp(e);
        }
        double P = blockReduce1024(loc, shD);
        double lpdf = (a-1.0)*lnx - x - (lga1 - log(a));
        double pdf = exp(lpdf);
        if (pdf < 1e-300) pdf = 1e-300;
        double xn = x - (P - p)/pdf;
        if (!(xn > 0.5*x)) xn = 0.5*x;
        if (xn > 2.0*x) xn = 2.0*x;
        x = xn;
    }
    if (t==0){
        out[0] = (float)testStat;
        out[1] = (float)(bet*x);
    }
}

// ----------------------------------------------------------------------------
extern "C" void kernel_launch(void* const* d_in, const int* in_sizes, int n_in,
                              void* d_out, int out_size) {
    const float* X = (const float*)d_in[0];
    const float* Y = (const float*)d_in[1];
    float* out = (float*)d_out;
    (void)in_sizes; (void)n_in; (void)out_size;

    k_init<<<1024, 256>>>(X, Y);
    k_dist<<<dim3(TILES,2), 256>>>(X, Y);
    k_hist2<<<dim3(TILES,2), 256>>>();
    k_sel2<<<1, 1024>>>();                       // profile slot 4
    k_rowsum<<<dim3(TILES,2), 256>>>();
    k_main<<<TILES, 256>>>();
    k_final<<<1, 1024>>>(out);
}

// round 9
// speedup vs baseline: 2.2037x; 1.0823x over previous
#include <cuda_runtime.h>
#include <math.h>
#include <stdint.h>

#define Nn    4096
#define DIMS  64
#define NB1   1024
#define SH1   16
#define NB2   131072           /* two 65536-key exact regions */
#define KB    0xC0800000u      /* f2k(4.0f) */
#define SPAN1 0x04000000u      /* 2^26 keys: values [4,1024) */
/* ranks (0-indexed, ascending) of the two triu-median values in the FULL
   n^2 multiset: triu ranks m/2-1, m/2 (m=n(n-1)/2) each doubled, plus
   4096 diagonal (~0) entries below everything */
#define R_LO 8390655u
#define R_HI 8390656u
#define TNT   32               /* tile grid dim: 4096/128 */
#define TILES 528              /* upper-tri tiles incl diagonal */
#define TSZ   16384            /* floats per 128x128 tile */

// ---- device scratch. Accumulated state is re-zeroed by k_main/k_final tails
// ---- each call; first call relies on .bss zero-init. ------------------------
__device__ float    g_D[2][TILES*TSZ];   // TILED layout: tile q contiguous
__device__ unsigned g_hist1[2][NB1];
__device__ unsigned g_below1[2];
__device__ unsigned g_hist2[2][NB2];
__device__ unsigned g_C[2][1024];        // 128-bin chunk sums of hist2
__device__ unsigned g_below2[2];
__device__ float    g_c[2];              // -log2(e)/median
__device__ double   g_rowd[2][Nn];
__device__ double   g_totd[2];
__device__ double   g_part[5][TILES];

__device__ __forceinline__ unsigned f2k(float f){
    unsigned u = __float_as_uint(f);
    return (u & 0x80000000u) ? ~u : (u | 0x80000000u);
}
__device__ __forceinline__ float k2f(unsigned k){
    unsigned u = (k & 0x80000000u) ? (k & 0x7FFFFFFFu) : ~k;
    return __uint_as_float(u);
}
// decode linear upper-triangle tile index -> (bi,bj), bi<=bj
__device__ __forceinline__ void tri_decode(int q, int &bi, int &bj){
    int b = (int)((65.0 - sqrt(65.0*65.0 - 8.0*(double)q))*0.5);
    if (b > TNT-1) b = TNT-1;
    while (b*(2*TNT+1-b)/2 > q) b--;
    while ((b+1)*(2*TNT+1-(b+1))/2 <= q) b++;
    bi = b; bj = b + (q - b*(2*TNT+1-b)/2);
}

// ---- shfl-based inclusive block scan (<=1024 threads, mult of 32) ----------
__device__ __forceinline__ unsigned blockScanU(unsigned v, unsigned* ws){
    int lane = threadIdx.x & 31, warp = threadIdx.x >> 5;
    __syncthreads();
    if (threadIdx.x < 32) ws[threadIdx.x] = 0u;
    __syncthreads();
    unsigned x = v;
    #pragma unroll
    for (int off=1; off<32; off<<=1){
        unsigned y = __shfl_up_sync(0xffffffffu, x, off);
        if (lane >= off) x += y;
    }
    if (lane==31) ws[warp] = x;
    __syncthreads();
    if (warp==0){
        unsigned w = ws[lane];
        #pragma unroll
        for (int off=1; off<32; off<<=1){
            unsigned y = __shfl_up_sync(0xffffffffu, w, off);
            if (lane >= off) w += y;
        }
        ws[lane] = w;
    }
    __syncthreads();
    unsigned base = warp ? ws[warp-1] : 0u;
    return base + x;
}

// ---- upper-tri distance tiles: D = Gi+Gj-2*dot, fused norms + fused hist ---
__global__ void __launch_bounds__(256) k_dist(const float* __restrict__ X,
                                              const float* __restrict__ Y){
    const int mat = blockIdx.y;
    const float* A = mat ? Y : X;
    float* Dt = g_D[mat] + (size_t)blockIdx.x * TSZ;
    int bi, bj; tri_decode(blockIdx.x, bi, bj);
    int i0 = bi*128, j0 = bj*128;
    __shared__ float As[128][33];
    __shared__ float Bs[128][33];
    __shared__ float Gi[128], Gj[128];
    __shared__ unsigned hb[NB1+1];    // [NB1] = below-4.0 counter
    int t = threadIdx.x;
    int tx = t & 15, ty = t >> 4;
    for (int b=t; b<NB1+1; b+=256) hb[b]=0u;

    float acc[8][8];
    #pragma unroll
    for (int a=0;a<8;a++)
        #pragma unroll
        for (int b=0;b<8;b++) acc[a][b]=0.0f;
    float nrm = 0.0f;

    for (int kk=0; kk<64; kk+=32){
        __syncthreads();
        #pragma unroll
        for (int it=0; it<4; it++){
            int l = t + it*256;          // 0..1023 float4 slots
            int r = l >> 3, c4 = l & 7;
            float4 va = *(const float4*)&A[(i0+r)*DIMS + kk + c4*4];
            As[r][c4*4+0]=va.x; As[r][c4*4+1]=va.y; As[r][c4*4+2]=va.z; As[r][c4*4+3]=va.w;
            float4 vb = *(const float4*)&A[(j0+r)*DIMS + kk + c4*4];
            Bs[r][c4*4+0]=vb.x; Bs[r][c4*4+1]=vb.y; Bs[r][c4*4+2]=vb.z; Bs[r][c4*4+3]=vb.w;
        }
        __syncthreads();
        {   // fused row norms: threads 0-127 do Gi rows, 128-255 do Gj rows
            int r = t & 127;
            const float (*S)[33] = (t < 128) ? As : Bs;
            float s = 0.0f;
            #pragma unroll 8
            for (int k=0;k<32;k++){ float v = S[r][k]; s += v*v; }
            nrm += s;
        }
        #pragma unroll 8
        for (int k=0;k<32;k++){
            float ar[8], br[8];
            #pragma unroll
            for (int a=0;a<8;a++) ar[a] = As[ty+16*a][k];
            #pragma unroll
            for (int b=0;b<8;b++) br[b] = Bs[tx+16*b][k];
            #pragma unroll
            for (int a=0;a<8;a++)
                #pragma unroll
                for (int b=0;b<8;b++) acc[a][b] += ar[a]*br[b];
        }
    }
    if (t < 128) Gi[t] = nrm; else Gj[t-128] = nrm;
    __syncthreads();

    unsigned w = (bi==bj) ? 1u : 2u;
    float gi[8], gj[8];
    #pragma unroll
    for (int a=0;a<8;a++) gi[a] = Gi[ty+16*a];
    #pragma unroll
    for (int b=0;b<8;b++) gj[b] = Gj[tx+16*b];
    #pragma unroll
    for (int a=0;a<8;a++){
        #pragma unroll
        for (int b=0;b<8;b++){
            float v = gi[a] + gj[b] - 2.0f*acc[a][b];
            Dt[(ty+16*a)*128 + tx+16*b] = v;
            unsigned key = f2k(v);
            unsigned off = key - KB;
            if (off < SPAN1) atomicAdd(&hb[off>>SH1], w);
            else if (key < KB) atomicAdd(&hb[NB1], w);
        }
    }
    __syncthreads();
    for (int b=t; b<NB1; b+=256)
        if (hb[b]) atomicAdd(&g_hist1[mat][b], hb[b]);
    if (t==0 && hb[NB1]) atomicAdd(&g_below1[mat], hb[NB1]);
}

// ---- per-block window derivation from hist1 (256 threads, deterministic) ---
__device__ void find_windows(int mat, unsigned &W1, unsigned &W2,
                             unsigned* ws, int* shB){
    int t = threadIdx.x;
    if (t==0){ shB[0]=-1; shB[1]=-1; }
    unsigned c0[4]; unsigned local=0;
    #pragma unroll
    for (int q=0;q<4;q++){ c0[q]=g_hist1[mat][t*4+q]; local+=c0[q]; }
    unsigned incl = blockScanU(local, ws);
    unsigned run = g_below1[mat] + (incl-local);
    #pragma unroll
    for (int q=0;q<4;q++){
        unsigned lo=run, hi=run+c0[q];
        if (c0[q]){
            if (lo<=R_LO && R_LO<hi) shB[0]=t*4+q;
            if (lo<=R_HI && R_HI<hi) shB[1]=t*4+q;
        }
        run=hi;
    }
    __syncthreads();
    int b1=shB[0], b2=shB[1];
    if (b1<0) b1 = (b2>=0)? b2 : NB1/2;
    if (b2<0) b2 = b1;
    if (b2==b1) b2 = b1+1;                        // keep regions disjoint
    W1 = KB + ((unsigned)b1 << SH1);
    W2 = KB + ((unsigned)b2 << SH1);
    __syncthreads();
}

// -- exact pass: per-key hist in 2 regions + chunk sums (flat, weighted) -----
__global__ void k_hist2(){
    int mat = blockIdx.y;
    __shared__ unsigned ws[32];
    __shared__ int shB[2];
    unsigned W1, W2;
    find_windows(mat, W1, W2, ws, shB);

    int bi, bj; tri_decode(blockIdx.x, bi, bj);
    unsigned w = (bi==bj) ? 1u : 2u;
    const float4* D4 = (const float4*)(g_D[mat] + (size_t)blockIdx.x * TSZ);
    int t = threadIdx.x;
    unsigned below = 0;
    #pragma unroll 8
    for (int it=0; it<16; it++){
        float4 d = D4[t + it*256];
        #pragma unroll
        for (int c=0;c<4;c++){
            float val = (c==0)?d.x:(c==1)?d.y:(c==2)?d.z:d.w;
            unsigned key = f2k(val);
            unsigned o1 = key - W1;
            if (o1 < 65536u){
                atomicAdd(&g_hist2[mat][o1], w);
                atomicAdd(&g_C[mat][o1>>7], w);
            } else {
                unsigned o2 = key - W2;
                if (o2 < 65536u){
                    atomicAdd(&g_hist2[mat][65536u+o2], w);
                    atomicAdd(&g_C[mat][512u+(o2>>7)], w);
                }
                else if (key < W1) below += w;
            }
        }
    }
    int lane = t & 31, warp = t >> 5;
    #pragma unroll
    for (int off=16; off; off>>=1) below += __shfl_xor_sync(0xffffffffu, below, off);
    __shared__ unsigned sb[8];
    if (lane==0) sb[warp]=below;
    __syncthreads();
    if (t==0){
        unsigned s=0;
        for (int q=0;q<8;q++) s+=sb[q];
        if (s) atomicAdd(&g_below2[mat], s);
    }
}

// -- exact median keys: light scans over hist1/C + parallel drill-down -------
__global__ void k_sel2(){
    __shared__ unsigned ws[32];
    __shared__ int sB1, sB2;          // coarse bins
    __shared__ int sq1, sq2;          // target chunks
    __shared__ unsigned sr1, sr2;     // exclusive rank at chunk start
    __shared__ int so1, so2;          // final bin offsets
    int t = threadIdx.x;
    for (int m=0;m<2;m++){
        if (t==0){ sB1=-1; sB2=-1; sq1=-1; sq2=-1; so1=-1; so2=-1; }
        // ---- derive W1/W2 from hist1 ----
        unsigned c1 = g_hist1[m][t];
        unsigned incl = blockScanU(c1, ws);
        {
            unsigned lo = g_below1[m] + (incl-c1);
            if (c1){
                if (lo<=R_LO && R_LO<lo+c1) sB1=t;
                if (lo<=R_HI && R_HI<lo+c1) sB2=t;
            }
        }
        __syncthreads();
        int b1=sB1, b2=sB2;
        if (b1<0) b1=(b2>=0)?b2:NB1/2;
        if (b2<0) b2=b1;
        if (b2==b1) b2=b1+1;
        unsigned W1 = KB + ((unsigned)b1<<SH1);
        unsigned W2 = KB + ((unsigned)b2<<SH1);
        // ---- scan chunk sums C, locate target chunks ----
        unsigned cc = g_C[m][t];
        unsigned incl2 = blockScanU(cc, ws);
        {
            unsigned lo = g_below2[m] + (incl2-cc);
            unsigned hi = lo + cc;
            if (cc){
                if (lo<=R_LO && R_LO<hi){ sq1=t; sr1=lo; }
                if (lo<=R_HI && R_HI<hi){ sq2=t; sr2=lo; }
            }
        }
        __syncthreads();
        // ---- parallel drill inside target chunks ----
        for (int which=0; which<2; which++){
            int sq = which ? sq2 : sq1;
            unsigned sr = which ? sr2 : sr1;
            unsigned RR = which ? R_HI : R_LO;
            if (sq >= 0){
                unsigned cnt = (t<128) ? g_hist2[m][sq*128+t] : 0u;
                unsigned icl = blockScanU(cnt, ws);
                if (t<128 && cnt){
                    unsigned lo = sr + (icl-cnt);
                    if (lo<=RR && RR<lo+cnt){
                        if (which) so2 = sq*128+t; else so1 = sq*128+t;
                    }
                }
                __syncthreads();
            }
        }
        if (t==0){
            int o1=so1, o2=so2;
            if (o1<0 && o2>=0) o1=o2;
            if (o2<0 && o1>=0) o2=o1;
            if (o1<0){ o1=32768; o2=32768; }         // unreachable safety
            unsigned k1 = (o1<65536)? W1+(unsigned)o1 : W2+(unsigned)(o1-65536);
            unsigned k2 = (o2<65536)? W1+(unsigned)o2 : W2+(unsigned)(o2-65536);
            float med = 0.5f*(k2f(k1)+k2f(k2));      // median == 2*width^2
            g_c[m] = -(float)(1.4426950408889634 / (double)med);
        }
        __syncthreads();
    }
}

// ----- row sums + tile totals from upper tiles ------------------------------
__global__ void k_rowsum(){
    int mat = blockIdx.y;
    int bi, bj; tri_decode(blockIdx.x, bi, bj);
    int i0 = bi*128, j0 = bj*128;
    float c = g_c[mat];
    const float* Dt = g_D[mat] + (size_t)blockIdx.x * TSZ;
    int warp = threadIdx.x >> 5, lane = threadIdx.x & 31;
    float ca0=0.f, ca1=0.f, ca2=0.f, ca3=0.f;
    #pragma unroll 4
    for (int it=0; it<16; it++){
        int r = warp + it*8;
        float4 d = *(const float4*)&Dt[r*128 + lane*4];
        float e0=exp2f(d.x*c), e1=exp2f(d.y*c), e2=exp2f(d.z*c), e3=exp2f(d.w*c);
        float rs = (e0+e1)+(e2+e3);
        #pragma unroll
        for (int off=16; off; off>>=1) rs += __shfl_xor_sync(0xffffffffu, rs, off);
        if (lane==0) atomicAdd(&g_rowd[mat][i0+r], (double)rs);
        ca0+=e0; ca1+=e1; ca2+=e2; ca3+=e3;
    }
    // tile total (each element once) -> g_totd with weight
    {
        __shared__ double sd[256];
        double ts = (double)ca0+(double)ca1+(double)ca2+(double)ca3;
        sd[threadIdx.x]=ts; __syncthreads();
        for (int off=128; off; off>>=1){
            if (threadIdx.x<off) sd[threadIdx.x]+=sd[threadIdx.x+off];
            __syncthreads();
        }
        if (threadIdx.x==0)
            atomicAdd(&g_totd[mat], (bi==bj?1.0:2.0)*sd[0]);
        __syncthreads();
    }
    if (bi != bj){
        __shared__ float cs[8][128];
        cs[warp][lane*4+0]=ca0; cs[warp][lane*4+1]=ca1;
        cs[warp][lane*4+2]=ca2; cs[warp][lane*4+3]=ca3;
        __syncthreads();
        if (threadIdx.x < 128){
            float s=0.f;
            #pragma unroll
            for (int q=0;q<8;q++) s += cs[q][threadIdx.x];
            atomicAdd(&g_rowd[mat][j0+threadIdx.x], (double)s);
        }
    }
}

__device__ double blockReduce256(double v, double* sh){
    int t = threadIdx.x;
    sh[t]=v; __syncthreads();
    for (int off=128; off; off>>=1){
        if (t<off) sh[t]+=sh[t+off];
        __syncthreads();
    }
    double r = sh[0]; __syncthreads();
    return r;
}
__device__ double blockReduce1024(double v, double* sh){
    int t = threadIdx.x;
    sh[t]=v; __syncthreads();
    for (int off=512; off; off>>=1){
        if (t<off) sh[t]+=sh[t+off];
        __syncthreads();
    }
    double r = sh[0]; __syncthreads();
    return r;
}

// -- fused centered-product over upper tiles + state-zeroing tail ------------
__global__ void k_main(){
    int bi, bj; tri_decode(blockIdx.x, bi, bj);
    int i0 = bi*128, j0 = bj*128;
    bool diag = (bi==bj);
    __shared__ double sd[256];
    int t = threadIdx.x;
    const double invn  = 1.0/(double)Nn;
    const double invn2 = invn*invn;
    float tmK = (float)(g_totd[0]*invn2);
    float tmL = (float)(g_totd[1]*invn2);

    float cX=g_c[0], cY=g_c[1];
    int warp = t >> 5, lane = t & 31;
    float rmKj[4], rmLj[4];
    #pragma unroll
    for (int q=0;q<4;q++){
        rmKj[q] = (float)(__ldg(&g_rowd[0][j0+lane*4+q])*invn);
        rmLj[q] = (float)(__ldg(&g_rowd[1][j0+lane*4+q])*invn);
    }
    const float* DX = g_D[0] + (size_t)blockIdx.x * TSZ;
    const float* DY = g_D[1] + (size_t)blockIdx.x * TSZ;
    float s1=0.f, s2=0.f, s2d=0.f, trk=0.f, trl=0.f;
    #pragma unroll 2
    for (int it=0; it<8; it++){
        int r = warp + it*16;
        float4 dxa = *(const float4*)&DX[r*128 + lane*4];
        float4 dya = *(const float4*)&DY[r*128 + lane*4];
        float4 dxb = *(const float4*)&DX[(r+8)*128 + lane*4];
        float4 dyb = *(const float4*)&DY[(r+8)*128 + lane*4];
        float rmKa = (float)(__ldg(&g_rowd[0][i0+r])*invn);
        float rmLa = (float)(__ldg(&g_rowd[1][i0+r])*invn);
        float rmKb = (float)(__ldg(&g_rowd[0][i0+r+8])*invn);
        float rmLb = (float)(__ldg(&g_rowd[1][i0+r+8])*invn);
        #pragma unroll
        for (int half=0; half<2; half++){
            float4 dx = half?dxb:dxa;
            float4 dy = half?dyb:dya;
            float rmKi = half?rmKb:rmKa;
            float rmLi = half?rmLb:rmLa;
            int rr = r + half*8;
            #pragma unroll
            for (int c=0;c<4;c++){
                float dxx = (c==0)?dx.x:(c==1)?dx.y:(c==2)?dx.z:dx.w;
                float dyy = (c==0)?dy.x:(c==1)?dy.y:(c==2)?dy.z:dy.w;
                float k = exp2f(dxx*cX);
                float l = exp2f(dyy*cY);
                float kc = k - rmKi - rmKj[c] + tmK;
                float lc = l - rmLi - rmLj[c] + tmL;
                float pr = kc*lc;
                s1 += pr;
                float p6 = pr*(1.0f/6.0f);
                float p66 = p6*p6;
                s2 += p66;
                if (diag && rr == lane*4+c){ s2d += p66; trk += k; trl += l; }
            }
        }
    }
    double wgt = diag ? 1.0 : 2.0;
    double vals[5] = {wgt*(double)s1, wgt*(double)s2, (double)s2d, (double)trk, (double)trl};
    for (int q=0;q<5;q++){
        double r = blockReduce256(vals[q], sd);
        if (t==0) g_part[q][blockIdx.x]=r;
    }
    // ---- zero accumulated state for the NEXT kernel_launch call ----
    int gidx = blockIdx.x*256 + t;                    // 0..135167
    for (int z = gidx; z < 2*NB2; z += TILES*256) ((unsigned*)g_hist2)[z] = 0u;
    if (gidx < 2*NB1) ((unsigned*)g_hist1)[gidx] = 0u;
    if (gidx < 2048)  ((unsigned*)g_C)[gidx] = 0u;
    if (gidx < 2){ g_below1[gidx]=0u; g_below2[gidx]=0u; }
}

// --------- final scalars + gamma quantile (parallel-series Newton) ----------
__global__ void k_final(float* out){
    __shared__ double shD[1024];
    __shared__ double S[4096];
    int t = threadIdx.x;
    double red[5];
    for (int q=0;q<5;q++){
        double s=0.0;
        for (int k=t;k<TILES;k+=1024) s += g_part[q][k];
        red[q] = blockReduce1024(s, shD);
    }
    double totK = g_totd[0], totL = g_totd[1];

    const double n = (double)Nn;
    double S1=red[0], S2=red[1], S2d=red[2], trK=red[3], trL=red[4];
    double testStat = S1/n;
    double varHSIC = (S2 - S2d)/(n*(n-1.0));
    varHSIC = varHSIC * 72.0*(n-4.0)*(n-5.0)/(n*(n-1.0)*(n-2.0)*(n-3.0));
    double muX = (totK-trK)/(n*(n-1.0));
    double muY = (totL-trL)/(n*(n-1.0));
    double mHSIC = (1.0 + muX*muY - muX - muY)/n;
    double a = mHSIC*mHSIC/varHSIC;
    double bet = varHSIC*n/mHSIC;

    // S_k = sum_{j=1..k} ln(a+j), k = 0..4095 (block prefix scan)
    double lg[4];
    #pragma unroll
    for (int q=0;q<4;q++) lg[q] = log(a + (double)(4*t+q+1));
    double part = lg[0]+lg[1]+lg[2]+lg[3];
    shD[t]=part; __syncthreads();
    for (int off=1; off<1024; off<<=1){
        double v = (t>=off) ? shD[t-off] : 0.0;
        __syncthreads(); shD[t]+=v; __syncthreads();
    }
    double excl = shD[t]-part;
    S[4*t]   = excl;
    S[4*t+1] = excl+lg[0];
    S[4*t+2] = excl+lg[0]+lg[1];
    S[4*t+3] = excl+lg[0]+lg[1]+lg[2];
    __syncthreads();

    double lga1 = lgamma(a+1.0);
    const double p = 0.2;                       // 1 - ALPH
    double z = -0.8416212335729143;             // Phi^-1(0.2)
    double u = 1.0 - 1.0/(9.0*a) + z/(3.0*sqrt(a));
    double x = a*u*u*u;
    if (!(x > 1e-8)) x = 0.5*a + 1e-3;
    for (int it=0; it<2; it++){
        double lnx = log(x);
        double b0 = a*lnx - x - lga1;
        double loc = 0.0;
        #pragma unroll
        for (int q=0;q<4;q++){
            int k = 4*t+q;
            double e = b0 + (double)k*lnx - S[k];
            if (e > -45.0) loc += exp(e);
        }
        double P = blockReduce1024(loc, shD);
        double lpdf = (a-1.0)*lnx - x - (lga1 - log(a));
        double pdf = exp(lpdf);
        if (pdf < 1e-300) pdf = 1e-300;
        double xn = x - (P - p)/pdf;
        if (!(xn > 0.5*x)) xn = 0.5*x;
        if (xn > 2.0*x) xn = 2.0*x;
        x = xn;
    }
    if (t==0){
        out[0] = (float)testStat;
        out[1] = (float)(bet*x);
    }
    // ---- zero remaining accumulated state for the next call ----
    for (int k=t; k<2*Nn; k+=1024) ((double*)g_rowd)[k]=0.0;
    if (t<2) g_totd[t]=0.0;
}

// ----------------------------------------------------------------------------
extern "C" void kernel_launch(void* const* d_in, const int* in_sizes, int n_in,
                              void* d_out, int out_size) {
    const float* X = (const float*)d_in[0];
    const float* Y = (const float*)d_in[1];
    float* out = (float*)d_out;
    (void)in_sizes; (void)n_in; (void)out_size;

    k_dist<<<dim3(TILES,2), 256>>>(X, Y);
    k_hist2<<<dim3(TILES,2), 256>>>();
    k_sel2<<<1, 1024>>>();
    k_rowsum<<<dim3(TILES,2), 256>>>();          // profile slot 4
    k_main<<<TILES, 256>>>();
    k_final<<<1, 1024>>>(out);
}

// round 10
// speedup vs baseline: 2.2426x; 1.0176x over previous
#include <cuda_runtime.h>
#include <math.h>
#include <stdint.h>

#define Nn    4096
#define DIMS  64
#define NB1   1024
#define SH1   16
#define NB2   131072           /* two 65536-key exact regions */
#define KB    0xC0800000u      /* f2k(4.0f) */
#define SPAN1 0x04000000u      /* 2^26 keys: values [4,1024) */
/* ranks (0-indexed, ascending) of the two triu-median values in the FULL
   n^2 multiset: triu ranks m/2-1, m/2 (m=n(n-1)/2) each doubled, plus
   4096 diagonal (~0) entries below everything */
#define R_LO 8390655u
#define R_HI 8390656u
#define TNT   32               /* tile grid dim: 4096/128 */
#define TILES 528              /* upper-tri tiles incl diagonal */
#define TSZ   16384            /* floats per 128x128 tile */

// ---- device scratch. Accumulated state is re-zeroed by k_main/k_final tails
// ---- each call; first call relies on .bss zero-init. ------------------------
__device__ float    g_D[2][TILES*TSZ];   // TILED: tile q contiguous; D then K in-place
__device__ unsigned g_hist1[2][NB1];
__device__ unsigned g_below1[2];
__device__ unsigned g_hist2[2][NB2];
__device__ unsigned g_C[2][1024];        // 128-bin chunk sums of hist2
__device__ unsigned g_below2[2];
__device__ double   g_rowd[2][Nn];
__device__ double   g_totd[2];
__device__ double   g_part[5][TILES];

__device__ __forceinline__ unsigned f2k(float f){
    unsigned u = __float_as_uint(f);
    return (u & 0x80000000u) ? ~u : (u | 0x80000000u);
}
__device__ __forceinline__ float k2f(unsigned k){
    unsigned u = (k & 0x80000000u) ? (k & 0x7FFFFFFFu) : ~k;
    return __uint_as_float(u);
}
// decode linear upper-triangle tile index -> (bi,bj), bi<=bj
__device__ __forceinline__ void tri_decode(int q, int &bi, int &bj){
    int b = (int)((65.0 - sqrt(65.0*65.0 - 8.0*(double)q))*0.5);
    if (b > TNT-1) b = TNT-1;
    while (b*(2*TNT+1-b)/2 > q) b--;
    while ((b+1)*(2*TNT+1-(b+1))/2 <= q) b++;
    bi = b; bj = b + (q - b*(2*TNT+1-b)/2);
}

// ---- shfl-based inclusive block scan (unsigned; <=1024 thr, mult of 32) ----
__device__ __forceinline__ unsigned blockScanU(unsigned v, unsigned* ws){
    int lane = threadIdx.x & 31, warp = threadIdx.x >> 5;
    __syncthreads();
    if (threadIdx.x < 32) ws[threadIdx.x] = 0u;
    __syncthreads();
    unsigned x = v;
    #pragma unroll
    for (int off=1; off<32; off<<=1){
        unsigned y = __shfl_up_sync(0xffffffffu, x, off);
        if (lane >= off) x += y;
    }
    if (lane==31) ws[warp] = x;
    __syncthreads();
    if (warp==0){
        unsigned w = ws[lane];
        #pragma unroll
        for (int off=1; off<32; off<<=1){
            unsigned y = __shfl_up_sync(0xffffffffu, w, off);
            if (lane >= off) w += y;
        }
        ws[lane] = w;
    }
    __syncthreads();
    unsigned base = warp ? ws[warp-1] : 0u;
    return base + x;
}
// ---- shfl-based inclusive block scan (double, 1024 threads) ----------------
__device__ __forceinline__ double blockScanD(double v, double* wsd){
    int lane = threadIdx.x & 31, warp = threadIdx.x >> 5;
    __syncthreads();
    if (threadIdx.x < 32) wsd[threadIdx.x] = 0.0;
    __syncthreads();
    double x = v;
    #pragma unroll
    for (int off=1; off<32; off<<=1){
        double y = __shfl_up_sync(0xffffffffu, x, off);
        if (lane >= off) x += y;
    }
    if (lane==31) wsd[warp] = x;
    __syncthreads();
    if (warp==0){
        double w = wsd[lane];
        #pragma unroll
        for (int off=1; off<32; off<<=1){
            double y = __shfl_up_sync(0xffffffffu, w, off);
            if (lane >= off) w += y;
        }
        wsd[lane] = w;
    }
    __syncthreads();
    return (warp ? wsd[warp-1] : 0.0) + x;
}

// ---- upper-tri distance tiles: D = Gi+Gj-2*dot, fused norms + fused hist ---
__global__ void __launch_bounds__(256) k_dist(const float* __restrict__ X,
                                              const float* __restrict__ Y){
    const int mat = blockIdx.y;
    const float* A = mat ? Y : X;
    float* Dt = g_D[mat] + (size_t)blockIdx.x * TSZ;
    int bi, bj; tri_decode(blockIdx.x, bi, bj);
    int i0 = bi*128, j0 = bj*128;
    __shared__ float As[128][33];
    __shared__ float Bs[128][33];
    __shared__ float Gi[128], Gj[128];
    __shared__ unsigned hb[NB1+1];    // [NB1] = below-4.0 counter
    int t = threadIdx.x;
    int tx = t & 15, ty = t >> 4;
    for (int b=t; b<NB1+1; b+=256) hb[b]=0u;

    float acc[8][8];
    #pragma unroll
    for (int a=0;a<8;a++)
        #pragma unroll
        for (int b=0;b<8;b++) acc[a][b]=0.0f;
    float nrm = 0.0f;

    for (int kk=0; kk<64; kk+=32){
        __syncthreads();
        #pragma unroll
        for (int it=0; it<4; it++){
            int l = t + it*256;          // 0..1023 float4 slots
            int r = l >> 3, c4 = l & 7;
            float4 va = *(const float4*)&A[(i0+r)*DIMS + kk + c4*4];
            As[r][c4*4+0]=va.x; As[r][c4*4+1]=va.y; As[r][c4*4+2]=va.z; As[r][c4*4+3]=va.w;
            float4 vb = *(const float4*)&A[(j0+r)*DIMS + kk + c4*4];
            Bs[r][c4*4+0]=vb.x; Bs[r][c4*4+1]=vb.y; Bs[r][c4*4+2]=vb.z; Bs[r][c4*4+3]=vb.w;
        }
        __syncthreads();
        {   // fused row norms: threads 0-127 do Gi rows, 128-255 do Gj rows
            int r = t & 127;
            const float (*S)[33] = (t < 128) ? As : Bs;
            float s = 0.0f;
            #pragma unroll 8
            for (int k=0;k<32;k++){ float v = S[r][k]; s += v*v; }
            nrm += s;
        }
        #pragma unroll 8
        for (int k=0;k<32;k++){
            float ar[8], br[8];
            #pragma unroll
            for (int a=0;a<8;a++) ar[a] = As[ty+16*a][k];
            #pragma unroll
            for (int b=0;b<8;b++) br[b] = Bs[tx+16*b][k];
            #pragma unroll
            for (int a=0;a<8;a++)
                #pragma unroll
                for (int b=0;b<8;b++) acc[a][b] += ar[a]*br[b];
        }
    }
    if (t < 128) Gi[t] = nrm; else Gj[t-128] = nrm;
    __syncthreads();

    unsigned w = (bi==bj) ? 1u : 2u;
    float gi[8], gj[8];
    #pragma unroll
    for (int a=0;a<8;a++) gi[a] = Gi[ty+16*a];
    #pragma unroll
    for (int b=0;b<8;b++) gj[b] = Gj[tx+16*b];
    #pragma unroll
    for (int a=0;a<8;a++){
        #pragma unroll
        for (int b=0;b<8;b++){
            float v = gi[a] + gj[b] - 2.0f*acc[a][b];
            Dt[(ty+16*a)*128 + tx+16*b] = v;
            unsigned key = f2k(v);
            unsigned off = key - KB;
            if (off < SPAN1) atomicAdd(&hb[off>>SH1], w);
            else if (key < KB) atomicAdd(&hb[NB1], w);
        }
    }
    __syncthreads();
    for (int b=t; b<NB1; b+=256)
        if (hb[b]) atomicAdd(&g_hist1[mat][b], hb[b]);
    if (t==0 && hb[NB1]) atomicAdd(&g_below1[mat], hb[NB1]);
}

// ---- per-block window derivation from hist1 (256 threads, deterministic) ---
__device__ void find_windows(int mat, unsigned &W1, unsigned &W2,
                             unsigned* ws, volatile int* shB){
    int t = threadIdx.x;
    if (t==0){ shB[0]=-1; shB[1]=-1; }
    unsigned c0[4]; unsigned local=0;
    #pragma unroll
    for (int q=0;q<4;q++){ c0[q]=g_hist1[mat][t*4+q]; local+=c0[q]; }
    unsigned incl = blockScanU(local, ws);
    unsigned run = g_below1[mat] + (incl-local);
    #pragma unroll
    for (int q=0;q<4;q++){
        if (c0[q]){
            if (run<=R_LO && R_LO<run+c0[q]) shB[0]=t*4+q;
            if (run<=R_HI && R_HI<run+c0[q]) shB[1]=t*4+q;
        }
        run += c0[q];
    }
    __syncthreads();
    int b1=shB[0], b2=shB[1];
    if (b1<0) b1 = (b2>=0)? b2 : NB1/2;
    if (b2<0) b2 = b1;
    if (b2==b1) b2 = b1+1;                        // keep regions disjoint
    W1 = KB + ((unsigned)b1 << SH1);
    W2 = KB + ((unsigned)b2 << SH1);
    __syncthreads();
}

// -- exact pass: per-key hist in 2 regions + chunk sums (flat, weighted) -----
__global__ void k_hist2(){
    int mat = blockIdx.y;
    __shared__ unsigned ws[32];
    __shared__ int shB[2];
    unsigned W1, W2;
    find_windows(mat, W1, W2, ws, shB);

    int bi, bj; tri_decode(blockIdx.x, bi, bj);
    unsigned w = (bi==bj) ? 1u : 2u;
    const float4* D4 = (const float4*)(g_D[mat] + (size_t)blockIdx.x * TSZ);
    int t = threadIdx.x;
    unsigned below = 0;
    #pragma unroll 8
    for (int it=0; it<16; it++){
        float4 d = D4[t + it*256];
        #pragma unroll
        for (int c=0;c<4;c++){
            float val = (c==0)?d.x:(c==1)?d.y:(c==2)?d.z:d.w;
            unsigned key = f2k(val);
            unsigned o1 = key - W1;
            if (o1 < 65536u){
                atomicAdd(&g_hist2[mat][o1], w);
                atomicAdd(&g_C[mat][o1>>7], w);
            } else {
                unsigned o2 = key - W2;
                if (o2 < 65536u){
                    atomicAdd(&g_hist2[mat][65536u+o2], w);
                    atomicAdd(&g_C[mat][512u+(o2>>7)], w);
                }
                else if (key < W1) below += w;
            }
        }
    }
    int lane = t & 31, warp = t >> 5;
    #pragma unroll
    for (int off=16; off; off>>=1) below += __shfl_xor_sync(0xffffffffu, below, off);
    __shared__ unsigned sb[8];
    if (lane==0) sb[warp]=below;
    __syncthreads();
    if (t==0){
        unsigned s=0;
        for (int q=0;q<8;q++) s+=sb[q];
        if (s) atomicAdd(&g_below2[mat], s);
    }
}

// -- per-block exact median -> c = -log2(e)/median (256 threads) -------------
__device__ float compute_c(int mat, unsigned* ws, volatile int* shi,
                           volatile unsigned* shu){
    int t = threadIdx.x;
    if (t==0){ shi[0]=-1; shi[1]=-1; shi[2]=-1; shi[3]=-1; shi[4]=-1; shi[5]=-1; }
    // windows from hist1
    unsigned c0[4]; unsigned loc=0;
    #pragma unroll
    for (int q=0;q<4;q++){ c0[q]=g_hist1[mat][t*4+q]; loc+=c0[q]; }
    unsigned incl = blockScanU(loc, ws);
    unsigned run = g_below1[mat] + (incl-loc);
    #pragma unroll
    for (int q=0;q<4;q++){
        if (c0[q]){
            if (run<=R_LO && R_LO<run+c0[q]) shi[0]=t*4+q;
            if (run<=R_HI && R_HI<run+c0[q]) shi[1]=t*4+q;
        }
        run += c0[q];
    }
    __syncthreads();
    int b1=shi[0], b2=shi[1];
    if (b1<0) b1=(b2>=0)?b2:NB1/2;
    if (b2<0) b2=b1;
    if (b2==b1) b2=b1+1;
    unsigned W1 = KB + ((unsigned)b1<<SH1);
    unsigned W2 = KB + ((unsigned)b2<<SH1);
    // locate target chunks from C
    unsigned c1[4]; unsigned loc2=0;
    #pragma unroll
    for (int q=0;q<4;q++){ c1[q]=g_C[mat][t*4+q]; loc2+=c1[q]; }
    unsigned incl2 = blockScanU(loc2, ws);
    unsigned run2 = g_below2[mat] + (incl2-loc2);
    #pragma unroll
    for (int q=0;q<4;q++){
        if (c1[q]){
            if (run2<=R_LO && R_LO<run2+c1[q]){ shi[2]=t*4+q; shu[0]=run2; }
            if (run2<=R_HI && R_HI<run2+c1[q]){ shi[3]=t*4+q; shu[1]=run2; }
        }
        run2 += c1[q];
    }
    __syncthreads();
    // parallel drill inside target chunks
    for (int which=0; which<2; which++){
        int sq = shi[2+which];
        unsigned sr = shu[which];
        unsigned RR = which ? R_HI : R_LO;
        if (sq >= 0){
            unsigned cnt = (t<128) ? g_hist2[mat][sq*128+t] : 0u;
            unsigned icl = blockScanU(cnt, ws);
            if (t<128 && cnt){
                unsigned lo = sr + (icl-cnt);
                if (lo<=RR && RR<lo+cnt) shi[4+which] = sq*128+t;
            }
            __syncthreads();
        }
    }
    int o1=shi[4], o2=shi[5];
    if (o1<0 && o2>=0) o1=o2;
    if (o2<0 && o1>=0) o2=o1;
    if (o1<0){ o1=32768; o2=32768; }               // unreachable safety
    unsigned k1 = (o1<65536)? W1+(unsigned)o1 : W2+(unsigned)(o1-65536);
    unsigned k2 = (o2<65536)? W1+(unsigned)o2 : W2+(unsigned)(o2-65536);
    float med = 0.5f*(k2f(k1)+k2f(k2));            // median == 2*width^2
    return -(float)(1.4426950408889634 / (double)med);
}

// -- rowsum + in-place D->K conversion (median recomputed per block) ---------
__global__ void k_rowsum(){
    int mat = blockIdx.y;
    __shared__ unsigned ws[32];
    __shared__ int shi[6];
    __shared__ unsigned shu[2];
    float c = compute_c(mat, ws, shi, shu);

    int bi, bj; tri_decode(blockIdx.x, bi, bj);
    int i0 = bi*128, j0 = bj*128;
    float* Dt = g_D[mat] + (size_t)blockIdx.x * TSZ;
    int warp = threadIdx.x >> 5, lane = threadIdx.x & 31;
    float ca0=0.f, ca1=0.f, ca2=0.f, ca3=0.f;
    #pragma unroll 4
    for (int it=0; it<16; it++){
        int r = warp + it*8;
        float4 d = *(float4*)&Dt[r*128 + lane*4];
        float e0=exp2f(d.x*c), e1=exp2f(d.y*c), e2=exp2f(d.z*c), e3=exp2f(d.w*c);
        float4 e; e.x=e0; e.y=e1; e.z=e2; e.w=e3;
        *(float4*)&Dt[r*128 + lane*4] = e;          // K overwrites D in place
        float rs = (e0+e1)+(e2+e3);
        #pragma unroll
        for (int off=16; off; off>>=1) rs += __shfl_xor_sync(0xffffffffu, rs, off);
        if (lane==0) atomicAdd(&g_rowd[mat][i0+r], (double)rs);
        ca0+=e0; ca1+=e1; ca2+=e2; ca3+=e3;
    }
    // tile total (each element once) -> g_totd with weight
    {
        double ts = (double)ca0+(double)ca1+(double)ca2+(double)ca3;
        #pragma unroll
        for (int off=16; off; off>>=1) ts += __shfl_xor_sync(0xffffffffu, ts, off);
        __shared__ double sd8[8];
        if (lane==0) sd8[warp]=ts;
        __syncthreads();
        if (threadIdx.x==0){
            double s=0.0;
            for (int q=0;q<8;q++) s+=sd8[q];
            atomicAdd(&g_totd[mat], (bi==bj?1.0:2.0)*s);
        }
        __syncthreads();
    }
    if (bi != bj){
        __shared__ float cs[8][128];
        cs[warp][lane*4+0]=ca0; cs[warp][lane*4+1]=ca1;
        cs[warp][lane*4+2]=ca2; cs[warp][lane*4+3]=ca3;
        __syncthreads();
        if (threadIdx.x < 128){
            float s=0.f;
            #pragma unroll
            for (int q=0;q<8;q++) s += cs[q][threadIdx.x];
            atomicAdd(&g_rowd[mat][j0+threadIdx.x], (double)s);
        }
    }
}

__device__ double blockReduce1024(double v, double* sh){
    int t = threadIdx.x;
    sh[t]=v; __syncthreads();
    for (int off=512; off; off>>=1){
        if (t<off) sh[t]+=sh[t+off];
        __syncthreads();
    }
    double r = sh[0]; __syncthreads();
    return r;
}

// -- fused centered-product over K/L tiles (no exp) + state-zeroing tail -----
__global__ void k_main(){
    int bi, bj; tri_decode(blockIdx.x, bi, bj);
    int i0 = bi*128, j0 = bj*128;
    bool diag = (bi==bj);
    int t = threadIdx.x;
    const double invn  = 1.0/(double)Nn;
    const double invn2 = invn*invn;
    float tmK = (float)(g_totd[0]*invn2);
    float tmL = (float)(g_totd[1]*invn2);

    int warp = t >> 5, lane = t & 31;
    float rmKj[4], rmLj[4];
    #pragma unroll
    for (int q=0;q<4;q++){
        rmKj[q] = (float)(__ldg(&g_rowd[0][j0+lane*4+q])*invn);
        rmLj[q] = (float)(__ldg(&g_rowd[1][j0+lane*4+q])*invn);
    }
    const float* KX = g_D[0] + (size_t)blockIdx.x * TSZ;
    const float* KY = g_D[1] + (size_t)blockIdx.x * TSZ;
    float s1=0.f, s2=0.f, s2d=0.f, trk=0.f, trl=0.f;
    #pragma unroll 2
    for (int it=0; it<8; it++){
        int r = warp + it*16;
        float4 kxa = *(const float4*)&KX[r*128 + lane*4];
        float4 kya = *(const float4*)&KY[r*128 + lane*4];
        float4 kxb = *(const float4*)&KX[(r+8)*128 + lane*4];
        float4 kyb = *(const float4*)&KY[(r+8)*128 + lane*4];
        float rmKa = (float)(__ldg(&g_rowd[0][i0+r])*invn);
        float rmLa = (float)(__ldg(&g_rowd[1][i0+r])*invn);
        float rmKb = (float)(__ldg(&g_rowd[0][i0+r+8])*invn);
        float rmLb = (float)(__ldg(&g_rowd[1][i0+r+8])*invn);
        #pragma unroll
        for (int half=0; half<2; half++){
            float4 kx = half?kxb:kxa;
            float4 ky = half?kyb:kya;
            float rmKi = half?rmKb:rmKa;
            float rmLi = half?rmLb:rmLa;
            int rr = r + half*8;
            #pragma unroll
            for (int c=0;c<4;c++){
                float k = (c==0)?kx.x:(c==1)?kx.y:(c==2)?kx.z:kx.w;
                float l = (c==0)?ky.x:(c==1)?ky.y:(c==2)?ky.z:ky.w;
                float kc = k - rmKi - rmKj[c] + tmK;
                float lc = l - rmLi - rmLj[c] + tmL;
                float pr = kc*lc;
                s1 += pr;
                float p6 = pr*(1.0f/6.0f);
                float p66 = p6*p6;
                s2 += p66;
                if (diag && rr == lane*4+c){ s2d += p66; trk += k; trl += l; }
            }
        }
    }
    double wgt = diag ? 1.0 : 2.0;
    double vals[5] = {wgt*(double)s1, wgt*(double)s2, (double)s2d, (double)trk, (double)trl};
    __shared__ double red[8][5];
    #pragma unroll
    for (int q=0;q<5;q++){
        double v = vals[q];
        #pragma unroll
        for (int off=16; off; off>>=1) v += __shfl_xor_sync(0xffffffffu, v, off);
        if (lane==0) red[warp][q]=v;
    }
    __syncthreads();
    if (t<5){
        double s=0.0;
        #pragma unroll
        for (int w=0;w<8;w++) s += red[w][t];
        g_part[t][blockIdx.x]=s;
    }
    // ---- zero accumulated state for the NEXT kernel_launch call ----
    int gidx = blockIdx.x*256 + t;                    // 0..135167
    for (int z = gidx; z < 2*NB2; z += TILES*256) ((unsigned*)g_hist2)[z] = 0u;
    if (gidx < 2*NB1) ((unsigned*)g_hist1)[gidx] = 0u;
    if (gidx < 2048)  ((unsigned*)g_C)[gidx] = 0u;
    if (gidx < 2){ g_below1[gidx]=0u; g_below2[gidx]=0u; }
}

// --------- final scalars + gamma quantile (parallel-series Newton) ----------
__global__ void k_final(float* out){
    __shared__ double shD[1024];
    __shared__ double S[4096];
    int t = threadIdx.x;
    double red[5];
    for (int q=0;q<5;q++){
        double s=0.0;
        for (int k=t;k<TILES;k+=1024) s += g_part[q][k];
        red[q] = blockReduce1024(s, shD);
    }
    double totK = g_totd[0], totL = g_totd[1];

    const double n = (double)Nn;
    double S1=red[0], S2=red[1], S2d=red[2], trK=red[3], trL=red[4];
    double testStat = S1/n;
    double varHSIC = (S2 - S2d)/(n*(n-1.0));
    varHSIC = varHSIC * 72.0*(n-4.0)*(n-5.0)/(n*(n-1.0)*(n-2.0)*(n-3.0));
    double muX = (totK-trK)/(n*(n-1.0));
    double muY = (totL-trL)/(n*(n-1.0));
    double mHSIC = (1.0 + muX*muY - muX - muY)/n;
    double a = mHSIC*mHSIC/varHSIC;
    double bet = varHSIC*n/mHSIC;

    // S_k = sum_{j=1..k} ln(a+j), k = 0..4095 (shfl block scan)
    double lg[4];
    #pragma unroll
    for (int q=0;q<4;q++) lg[q] = log(a + (double)(4*t+q+1));
    double part = lg[0]+lg[1]+lg[2]+lg[3];
    double incl = blockScanD(part, shD);
    double excl = incl-part;
    S[4*t]   = excl;
    S[4*t+1] = excl+lg[0];
    S[4*t+2] = excl+lg[0]+lg[1];
    S[4*t+3] = excl+lg[0]+lg[1]+lg[2];
    __syncthreads();

    double lga1 = lgamma(a+1.0);
    const double p = 0.2;                       // 1 - ALPH
    double z = -0.8416212335729143;             // Phi^-1(0.2)
    double u = 1.0 - 1.0/(9.0*a) + z/(3.0*sqrt(a));
    double x = a*u*u*u;
    if (!(x > 1e-8)) x = 0.5*a + 1e-3;
    for (int it=0; it<2; it++){
        double lnx = log(x);
        double b0 = a*lnx - x - lga1;
        double loc = 0.0;
        #pragma unroll
        for (int q=0;q<4;q++){
            int k = 4*t+q;
            double e = b0 + (double)k*lnx - S[k];
            if (e > -45.0) loc += exp(e);
        }
        double P = blockReduce1024(loc, shD);
        double lpdf = (a-1.0)*lnx - x - (lga1 - log(a));
        double pdf = exp(lpdf);
        if (pdf < 1e-300) pdf = 1e-300;
        double xn = x - (P - p)/pdf;
        if (!(xn > 0.5*x)) xn = 0.5*x;
        if (xn > 2.0*x) xn = 2.0*x;
        x = xn;
    }
    if (t==0){
        out[0] = (float)testStat;
        out[1] = (float)(bet*x);
    }
    // ---- zero remaining accumulated state for the next call ----
    for (int k=t; k<2*Nn; k+=1024) ((double*)g_rowd)[k]=0.0;
    if (t<2) g_totd[t]=0.0;
}

// ----------------------------------------------------------------------------
extern "C" void kernel_launch(void* const* d_in, const int* in_sizes, int n_in,
                              void* d_out, int out_size) {
    const float* X = (const float*)d_in[0];
    const float* Y = (const float*)d_in[1];
    float* out = (float*)d_out;
    (void)in_sizes; (void)n_in; (void)out_size;

    k_dist<<<dim3(TILES,2), 256>>>(X, Y);
    k_hist2<<<dim3(TILES,2), 256>>>();
    k_rowsum<<<dim3(TILES,2), 256>>>();
    k_main<<<TILES, 256>>>();                    // profile slot 4
    k_final<<<1, 1024>>>(out);
}